// round 1
// baseline (speedup 1.0000x reference)
#include <cuda_runtime.h>
#include <cuda_bf16.h>
#include <math.h>

// Problem dims (fixed by reference)
#define BATCH 2
#define SEQ 2048
#define DMODEL 2048
#define NH 16
#define NKV 4
#define HD 128
#define REP 4
#define NEG_INF_F (-1000000000.0f)

#define MTOK (BATCH * SEQ)          // 4096 tokens

// Scratch (device globals; allocation is forbidden)
__device__ float g_q[MTOK * NH * HD];    // [b,s,h,d] = [4096, 2048]
__device__ float g_k[MTOK * NKV * HD];   // [4096, 512]
__device__ float g_v[MTOK * NKV * HD];   // [4096, 512]
__device__ float g_ao[MTOK * NH * HD];   // attention output [4096, 2048]

// ---------------------------------------------------------------------------
// SGEMM: C[M,N] = A[M,K] @ B[K,N], row-major, fp32. BM=BN=128, BK=8,
// 256 threads, 8x8 per-thread register tile. Dims assumed divisible.
// ---------------------------------------------------------------------------
#define BM 128
#define BN 128
#define BKK 8

__global__ __launch_bounds__(256) void sgemm_kernel(
    const float* __restrict__ A, const float* __restrict__ B,
    float* __restrict__ C, int M, int N, int K) {
  __shared__ float As[BKK][BM];   // transposed A tile
  __shared__ float Bs[BKK][BN];

  const int tid = threadIdx.x;
  const int tr = tid >> 4;        // 0..15
  const int tc = tid & 15;        // 0..15
  const int row0 = blockIdx.y * BM;
  const int col0 = blockIdx.x * BN;

  float acc[8][8];
#pragma unroll
  for (int i = 0; i < 8; ++i)
#pragma unroll
    for (int j = 0; j < 8; ++j) acc[i][j] = 0.f;

  const int a_row = tid >> 1;           // 0..127
  const int a_kp = (tid & 1) * 4;       // 0 or 4
  const int b_k = tid >> 5;             // 0..7
  const int b_col = (tid & 31) * 4;     // 0..124

  for (int k0 = 0; k0 < K; k0 += BKK) {
    float4 av = *(const float4*)(A + (size_t)(row0 + a_row) * K + k0 + a_kp);
    As[a_kp + 0][a_row] = av.x;
    As[a_kp + 1][a_row] = av.y;
    As[a_kp + 2][a_row] = av.z;
    As[a_kp + 3][a_row] = av.w;
    *(float4*)&Bs[b_k][b_col] =
        *(const float4*)(B + (size_t)(k0 + b_k) * N + col0 + b_col);
    __syncthreads();
#pragma unroll
    for (int k = 0; k < BKK; ++k) {
      float4 a0 = *(const float4*)&As[k][tr * 8];
      float4 a1 = *(const float4*)&As[k][tr * 8 + 4];
      float4 b0 = *(const float4*)&Bs[k][tc * 8];
      float4 b1 = *(const float4*)&Bs[k][tc * 8 + 4];
      float ra[8] = {a0.x, a0.y, a0.z, a0.w, a1.x, a1.y, a1.z, a1.w};
      float rb[8] = {b0.x, b0.y, b0.z, b0.w, b1.x, b1.y, b1.z, b1.w};
#pragma unroll
      for (int i = 0; i < 8; ++i)
#pragma unroll
        for (int j = 0; j < 8; ++j) acc[i][j] += ra[i] * rb[j];
    }
    __syncthreads();
  }

#pragma unroll
  for (int i = 0; i < 8; ++i) {
    float* crow = C + (size_t)(row0 + tr * 8 + i) * N + col0 + tc * 8;
    float4 v0 = {acc[i][0], acc[i][1], acc[i][2], acc[i][3]};
    float4 v1 = {acc[i][4], acc[i][5], acc[i][6], acc[i][7]};
    *(float4*)(crow) = v0;
    *(float4*)(crow + 4) = v1;
  }
}

// ---------------------------------------------------------------------------
// RoPE: interleaved pairs; t layout [b, s, h, d]
// ---------------------------------------------------------------------------
__global__ void rope_kernel(float* __restrict__ t, const float* __restrict__ fcos,
                            const float* __restrict__ fsin, int nheads) {
  int idx = blockIdx.x * blockDim.x + threadIdx.x;
  int total = BATCH * SEQ * nheads * (HD / 2);
  if (idx >= total) return;
  int p = idx & 63;                 // pair index 0..63
  int rest = idx >> 6;
  int h = rest % nheads;
  rest /= nheads;
  int s = rest & (SEQ - 1);
  int b = rest >> 11;
  float c = fcos[s * 64 + p];
  float sn = fsin[s * 64 + p];
  float* base = t + ((size_t)(b * SEQ + s) * nheads + h) * HD + p * 2;
  float x0 = base[0], x1 = base[1];
  base[0] = x0 * c - x1 * sn;
  base[1] = x0 * sn + x1 * c;
}

// ---------------------------------------------------------------------------
// Flash attention, fp32, causal. BLOCK_M = BLOCK_N = 64, D = 128.
// grid: (SEQ/64, NH, BATCH), 256 threads.
// Q tile in smem (scaled), K tile stored TRANSPOSED (Kt[d][t]) for
// conflict-free QK^T reads, V tile row-major, S tile in smem for softmax.
// ---------------------------------------------------------------------------
#define FAM 64
#define FAN 64
#define QS_STRIDE 132     // 128 + 4 pad
#define KT_STRIDE 68      // 64 + 4 pad (16B aligned)
#define VS_STRIDE 132
#define SS_STRIDE 65

#define FA_SMEM_FLOATS (FAM * QS_STRIDE + HD * KT_STRIDE + FAN * VS_STRIDE + FAM * SS_STRIDE + 3 * FAM)
#define FA_SMEM_BYTES (FA_SMEM_FLOATS * 4)

__global__ __launch_bounds__(256) void fa_kernel(
    const float* __restrict__ q, const float* __restrict__ k,
    const float* __restrict__ v, float* __restrict__ o) {
  extern __shared__ float sm[];
  float* Qs = sm;                               // [64][132]
  float* Kt = Qs + FAM * QS_STRIDE;             // [128][68]
  float* Vs = Kt + HD * KT_STRIDE;              // [64][132]
  float* Ss = Vs + FAN * VS_STRIDE;             // [64][65]
  float* m_s = Ss + FAM * SS_STRIDE;            // [64]
  float* l_s = m_s + FAM;                       // [64]
  float* f_s = l_s + FAM;                       // [64]

  const int tid = threadIdx.x;
  const int m0 = blockIdx.x * FAM;
  const int h = blockIdx.y;
  const int b = blockIdx.z;
  const int g = h >> 2;                          // kv head
  const float scale = 0.08838834764831845f;      // 1/sqrt(128)

  // Load Q tile (pre-scaled)
  for (int i = tid; i < FAM * (HD / 4); i += 256) {
    int r = i >> 5;
    int cc = (i & 31) * 4;
    float4 vq = *(const float4*)(q + ((size_t)(b * SEQ + m0 + r) * NH + h) * HD + cc);
    vq.x *= scale; vq.y *= scale; vq.z *= scale; vq.w *= scale;
    *(float4*)&Qs[r * QS_STRIDE + cc] = vq;
  }
  if (tid < FAM) {
    m_s[tid] = -1e30f;
    l_s[tid] = 0.f;
  }

  const int tr = tid >> 4;   // 0..15
  const int tc = tid & 15;   // 0..15

  float acc[4][8];
#pragma unroll
  for (int i = 0; i < 4; ++i)
#pragma unroll
    for (int j = 0; j < 8; ++j) acc[i][j] = 0.f;

  const int n_tiles = blockIdx.x + 1;   // causal

  for (int t = 0; t < n_tiles; ++t) {
    const int n0 = t * FAN;
    __syncthreads();   // previous iter readers done; also covers Q/stat init
    // Load K tile transposed + V tile
    for (int i = tid; i < FAN * (HD / 4); i += 256) {
      int r = i >> 5;
      int cc = (i & 31) * 4;
      const float* kvbase = k + ((size_t)(b * SEQ + n0 + r) * NKV + g) * HD + cc;
      float4 vk = *(const float4*)kvbase;
      Kt[(cc + 0) * KT_STRIDE + r] = vk.x;
      Kt[(cc + 1) * KT_STRIDE + r] = vk.y;
      Kt[(cc + 2) * KT_STRIDE + r] = vk.z;
      Kt[(cc + 3) * KT_STRIDE + r] = vk.w;
      const float* vvbase = v + ((size_t)(b * SEQ + n0 + r) * NKV + g) * HD + cc;
      *(float4*)&Vs[r * VS_STRIDE + cc] = *(const float4*)vvbase;
    }
    __syncthreads();

    // GEMM1: S(4x4 per thread) = Qs @ Kt
    float s4[4][4];
#pragma unroll
    for (int i = 0; i < 4; ++i)
#pragma unroll
      for (int j = 0; j < 4; ++j) s4[i][j] = 0.f;

    for (int kk = 0; kk < HD; ++kk) {
      float qv0 = Qs[(tr * 4 + 0) * QS_STRIDE + kk];
      float qv1 = Qs[(tr * 4 + 1) * QS_STRIDE + kk];
      float qv2 = Qs[(tr * 4 + 2) * QS_STRIDE + kk];
      float qv3 = Qs[(tr * 4 + 3) * QS_STRIDE + kk];
      float4 kv = *(const float4*)&Kt[kk * KT_STRIDE + tc * 4];
      s4[0][0] += qv0 * kv.x; s4[0][1] += qv0 * kv.y; s4[0][2] += qv0 * kv.z; s4[0][3] += qv0 * kv.w;
      s4[1][0] += qv1 * kv.x; s4[1][1] += qv1 * kv.y; s4[1][2] += qv1 * kv.z; s4[1][3] += qv1 * kv.w;
      s4[2][0] += qv2 * kv.x; s4[2][1] += qv2 * kv.y; s4[2][2] += qv2 * kv.z; s4[2][3] += qv2 * kv.w;
      s4[3][0] += qv3 * kv.x; s4[3][1] += qv3 * kv.y; s4[3][2] += qv3 * kv.z; s4[3][3] += qv3 * kv.w;
    }
    // mask + store S
#pragma unroll
    for (int i = 0; i < 4; ++i) {
      int srow = m0 + tr * 4 + i;
#pragma unroll
      for (int j = 0; j < 4; ++j) {
        int scol = n0 + tc * 4 + j;
        float val = s4[i][j] + ((scol > srow) ? NEG_INF_F : 0.f);
        Ss[(tr * 4 + i) * SS_STRIDE + tc * 4 + j] = val;
      }
    }
    __syncthreads();

    // Phase A: per-row max, rescale factor
    if (tid < FAM) {
      float mx = -1e30f;
      for (int c = 0; c < FAN; ++c) mx = fmaxf(mx, Ss[tid * SS_STRIDE + c]);
      float mold = m_s[tid];
      float mnew = fmaxf(mold, mx);
      float f = __expf(mold - mnew);
      m_s[tid] = mnew;
      f_s[tid] = f;
      l_s[tid] *= f;
    }
    __syncthreads();

    // Phase B: exponentiate S, rescale accumulators
#pragma unroll
    for (int i = 0; i < 4; ++i) {
      int r = tr * 4 + i;
      float mnew = m_s[r];
#pragma unroll
      for (int j = 0; j < 4; ++j) {
        float* p = &Ss[r * SS_STRIDE + tc * 4 + j];
        *p = __expf(*p - mnew);
      }
    }
#pragma unroll
    for (int i = 0; i < 4; ++i) {
      float f = f_s[tr * 4 + i];
#pragma unroll
      for (int j = 0; j < 8; ++j) acc[i][j] *= f;
    }
    __syncthreads();

    // Phase C: row sums (threads < 64)
    if (tid < FAM) {
      float s = 0.f;
      for (int c = 0; c < FAN; ++c) s += Ss[tid * SS_STRIDE + c];
      l_s[tid] += s;
    }

    // GEMM2: acc += P @ V (4 rows x 8 cols per thread)
    for (int kk = 0; kk < FAN; ++kk) {
      float p0 = Ss[(tr * 4 + 0) * SS_STRIDE + kk];
      float p1 = Ss[(tr * 4 + 1) * SS_STRIDE + kk];
      float p2 = Ss[(tr * 4 + 2) * SS_STRIDE + kk];
      float p3 = Ss[(tr * 4 + 3) * SS_STRIDE + kk];
      float4 v0 = *(const float4*)&Vs[kk * VS_STRIDE + tc * 8];
      float4 v1 = *(const float4*)&Vs[kk * VS_STRIDE + tc * 8 + 4];
      acc[0][0] += p0 * v0.x; acc[0][1] += p0 * v0.y; acc[0][2] += p0 * v0.z; acc[0][3] += p0 * v0.w;
      acc[0][4] += p0 * v1.x; acc[0][5] += p0 * v1.y; acc[0][6] += p0 * v1.z; acc[0][7] += p0 * v1.w;
      acc[1][0] += p1 * v0.x; acc[1][1] += p1 * v0.y; acc[1][2] += p1 * v0.z; acc[1][3] += p1 * v0.w;
      acc[1][4] += p1 * v1.x; acc[1][5] += p1 * v1.y; acc[1][6] += p1 * v1.z; acc[1][7] += p1 * v1.w;
      acc[2][0] += p2 * v0.x; acc[2][1] += p2 * v0.y; acc[2][2] += p2 * v0.z; acc[2][3] += p2 * v0.w;
      acc[2][4] += p2 * v1.x; acc[2][5] += p2 * v1.y; acc[2][6] += p2 * v1.z; acc[2][7] += p2 * v1.w;
      acc[3][0] += p3 * v0.x; acc[3][1] += p3 * v0.y; acc[3][2] += p3 * v0.z; acc[3][3] += p3 * v0.w;
      acc[3][4] += p3 * v1.x; acc[3][5] += p3 * v1.y; acc[3][6] += p3 * v1.z; acc[3][7] += p3 * v1.w;
    }
  }
  __syncthreads();

  // Epilogue: normalize and write [b, s, h, d]
#pragma unroll
  for (int i = 0; i < 4; ++i) {
    int r = tr * 4 + i;
    float inv = 1.f / l_s[r];
    float* orow = o + ((size_t)(b * SEQ + m0 + r) * NH + h) * HD + tc * 8;
    float4 o0 = {acc[i][0] * inv, acc[i][1] * inv, acc[i][2] * inv, acc[i][3] * inv};
    float4 o1 = {acc[i][4] * inv, acc[i][5] * inv, acc[i][6] * inv, acc[i][7] * inv};
    *(float4*)(orow) = o0;
    *(float4*)(orow + 4) = o1;
  }
}

// ---------------------------------------------------------------------------
// Launch
// ---------------------------------------------------------------------------
extern "C" void kernel_launch(void* const* d_in, const int* in_sizes, int n_in,
                              void* d_out, int out_size) {
  const float* x    = (const float*)d_in[0];
  const float* fcos = (const float*)d_in[1];
  const float* fsin = (const float*)d_in[2];
  // d_in[3] = mask (causal mask applied analytically)
  const float* wq = (const float*)d_in[4];
  const float* wk = (const float*)d_in[5];
  const float* wv = (const float*)d_in[6];
  const float* wo = (const float*)d_in[7];
  float* out = (float*)d_out;

  float *q, *k, *v, *ao;
  cudaGetSymbolAddress((void**)&q, g_q);
  cudaGetSymbolAddress((void**)&k, g_k);
  cudaGetSymbolAddress((void**)&v, g_v);
  cudaGetSymbolAddress((void**)&ao, g_ao);

  // Projections
  sgemm_kernel<<<dim3(DMODEL / BN, MTOK / BM), 256>>>(x, wq, q, MTOK, NH * HD, DMODEL);
  sgemm_kernel<<<dim3((NKV * HD) / BN, MTOK / BM), 256>>>(x, wk, k, MTOK, NKV * HD, DMODEL);
  sgemm_kernel<<<dim3((NKV * HD) / BN, MTOK / BM), 256>>>(x, wv, v, MTOK, NKV * HD, DMODEL);

  // RoPE
  {
    int tq = BATCH * SEQ * NH * (HD / 2);
    rope_kernel<<<(tq + 255) / 256, 256>>>(q, fcos, fsin, NH);
    int tk = BATCH * SEQ * NKV * (HD / 2);
    rope_kernel<<<(tk + 255) / 256, 256>>>(k, fcos, fsin, NKV);
  }

  // Flash attention
  cudaFuncSetAttribute(fa_kernel, cudaFuncAttributeMaxDynamicSharedMemorySize,
                       FA_SMEM_BYTES);
  fa_kernel<<<dim3(SEQ / FAM, NH, BATCH), 256, FA_SMEM_BYTES>>>(q, k, v, ao);

  // Output projection
  sgemm_kernel<<<dim3(DMODEL / BN, MTOK / BM), 256>>>(ao, wo, out, MTOK, DMODEL, DMODEL);
}

// round 4
// speedup vs baseline: 1.6172x; 1.6172x over previous
#include <cuda_runtime.h>
#include <cuda_bf16.h>
#include <cstdint>
#include <math.h>

// Problem dims (fixed by reference)
#define BATCH 2
#define SEQ 2048
#define DMODEL 2048
#define NH 16
#define NKV 4
#define HD 128
#define NEG_INF_F (-1000000000.0f)
#define MTOK (BATCH * SEQ)          // 4096 tokens
#define KVDIM (NKV * HD)            // 512

// ---------------------------------------------------------------------------
// Scratch (device globals; runtime allocation is forbidden)
// ---------------------------------------------------------------------------
__device__ float g_q[MTOK * NH * HD];
__device__ float g_k[MTOK * KVDIM];
__device__ float g_v[MTOK * KVDIM];
__device__ float g_ao[MTOK * NH * HD];

// split-precision bf16 operands
__device__ __nv_bfloat16 g_x_hi[MTOK * DMODEL];
__device__ __nv_bfloat16 g_x_lo[MTOK * DMODEL];
__device__ __nv_bfloat16 g_ao_hi[MTOK * DMODEL];
__device__ __nv_bfloat16 g_ao_lo[MTOK * DMODEL];
// weights transposed to [N, K]
__device__ __nv_bfloat16 g_wq_hi[DMODEL * DMODEL];
__device__ __nv_bfloat16 g_wq_lo[DMODEL * DMODEL];
__device__ __nv_bfloat16 g_wk_hi[KVDIM * DMODEL];
__device__ __nv_bfloat16 g_wk_lo[KVDIM * DMODEL];
__device__ __nv_bfloat16 g_wv_hi[KVDIM * DMODEL];
__device__ __nv_bfloat16 g_wv_lo[KVDIM * DMODEL];
__device__ __nv_bfloat16 g_wo_hi[DMODEL * DMODEL];
__device__ __nv_bfloat16 g_wo_lo[DMODEL * DMODEL];

// ---------------------------------------------------------------------------
// helpers
// ---------------------------------------------------------------------------
__device__ __forceinline__ uint32_t smem_u32(const void* p) {
  uint32_t a;
  asm("{ .reg .u64 t; cvta.to.shared.u64 t, %1; cvt.u32.u64 %0, t; }"
      : "=r"(a) : "l"(p));
  return a;
}
__device__ __forceinline__ void cpa16(uint32_t s, const void* g) {
  asm volatile("cp.async.cg.shared.global [%0], [%1], 16;"
               :: "r"(s), "l"(g) : "memory");
}
__device__ __forceinline__ void cpa_commit_wait0() {
  asm volatile("cp.async.commit_group;" ::: "memory");
  asm volatile("cp.async.wait_group 0;" ::: "memory");
}
__device__ __forceinline__ void ldsm_x4(uint32_t addr, uint32_t* r) {
  asm volatile("ldmatrix.sync.aligned.m8n8.x4.shared.b16 {%0,%1,%2,%3}, [%4];"
               : "=r"(r[0]), "=r"(r[1]), "=r"(r[2]), "=r"(r[3]) : "r"(addr));
}
__device__ __forceinline__ void mma_bf16(float* d, const uint32_t* a,
                                         const uint32_t* b) {
  asm volatile(
      "mma.sync.aligned.m16n8k16.row.col.f32.bf16.bf16.f32 "
      "{%0,%1,%2,%3}, {%4,%5,%6,%7}, {%8,%9}, {%0,%1,%2,%3};"
      : "+f"(d[0]), "+f"(d[1]), "+f"(d[2]), "+f"(d[3])
      : "r"(a[0]), "r"(a[1]), "r"(a[2]), "r"(a[3]), "r"(b[0]), "r"(b[1]));
}

// ---------------------------------------------------------------------------
// Split-precision conversion kernels
// ---------------------------------------------------------------------------
__global__ void split_kernel(const float* __restrict__ src,
                             __nv_bfloat16* __restrict__ hi,
                             __nv_bfloat16* __restrict__ lo, int n) {
  int i = blockIdx.x * blockDim.x + threadIdx.x;
  if (i >= n) return;
  float f = src[i];
  __nv_bfloat16 h = __float2bfloat16(f);
  hi[i] = h;
  lo[i] = __float2bfloat16(f - __bfloat162float(h));
}

// w[K,N] fp32 -> th/tl [N,K] bf16 (transpose + split)
__global__ void transpose_split_kernel(const float* __restrict__ w,
                                       __nv_bfloat16* __restrict__ th,
                                       __nv_bfloat16* __restrict__ tl,
                                       int K, int N) {
  __shared__ float tile[32][33];
  int nx = blockIdx.x * 32 + threadIdx.x;
  int k0 = blockIdx.y * 32;
  for (int i = threadIdx.y; i < 32; i += 8)
    tile[i][threadIdx.x] = w[(size_t)(k0 + i) * N + nx];
  __syncthreads();
  for (int j = threadIdx.y; j < 32; j += 8) {
    int n = blockIdx.x * 32 + j;
    int kk = k0 + threadIdx.x;
    float f = tile[threadIdx.x][j];
    __nv_bfloat16 h = __float2bfloat16(f);
    th[(size_t)n * K + kk] = h;
    tl[(size_t)n * K + kk] = __float2bfloat16(f - __bfloat162float(h));
  }
}

// ---------------------------------------------------------------------------
// mma.sync bf16 split-precision GEMM: C[M,N] = A[M,K] @ Bt[N,K]^T
// 128x128 CTA tile, BK=64, 256 thr, 8 warps (warp tile 32x64).
// ---------------------------------------------------------------------------
#define SA 72                        // smem row stride (elements)
#define TILE_E (128 * SA)            // elements per tile
#define GEMM_SMEM (4 * TILE_E * 2)   // 4 tiles of bf16 = 73728 B

__global__ __launch_bounds__(256, 2) void gemm_mma_kernel(
    const __nv_bfloat16* __restrict__ Ahi, const __nv_bfloat16* __restrict__ Alo,
    const __nv_bfloat16* __restrict__ Bhi, const __nv_bfloat16* __restrict__ Blo,
    float* __restrict__ C, int M, int N, int K) {
  extern __shared__ __nv_bfloat16 smb[];
  const int tid = threadIdx.x;
  const int lane = tid & 31;
  const int wid = tid >> 5;
  const int wm = wid & 3;            // 0..3 -> m offset wm*32
  const int wn = wid >> 2;           // 0..1 -> n offset wn*64
  const int m0 = blockIdx.y * 128;
  const int n0 = blockIdx.x * 128;
  const uint32_t sbase = smem_u32(smb);

  // tile element offsets
  const uint32_t OA_HI = 0, OA_LO = TILE_E, OB_HI = 2 * TILE_E, OB_LO = 3 * TILE_E;

  float acc[2][8][4];
#pragma unroll
  for (int i = 0; i < 2; ++i)
#pragma unroll
    for (int j = 0; j < 8; ++j)
#pragma unroll
      for (int q = 0; q < 4; ++q) acc[i][j][q] = 0.f;

  // ldmatrix lane address components (non-trans x4 maps)
  const int a_row = lane & 15;
  const int a_col = (lane >> 4) * 8;
  const int b_row = (lane & 7) + ((lane & 16) >> 1);   // n within 16
  const int b_col = lane & 8;                          // k 8-offset

  // load map: per tile, 4 vectors/thread; idx -> (row, col8)
  const int l_r = tid >> 3;          // base row, stride 32 per iter
  const int l_c = (tid & 7) * 8;     // bf16 col

  const int nchunks = K >> 6;        // K/64
  for (int c = 0; c < nchunks; ++c) {
    const int k0g = c << 6;
    if (c) __syncthreads();          // previous compute done before overwrite
#pragma unroll
    for (int q = 0; q < 4; ++q) {
      int r = l_r + q * 32;
      const size_t ga = (size_t)(m0 + r) * K + k0g + l_c;
      const size_t gb = (size_t)(n0 + r) * K + k0g + l_c;
      uint32_t so = (uint32_t)(r * SA + l_c) * 2;
      cpa16(sbase + (OA_HI * 2) + so, Ahi + ga);
      cpa16(sbase + (OA_LO * 2) + so, Alo + ga);
      cpa16(sbase + (OB_HI * 2) + so, Bhi + gb);
      cpa16(sbase + (OB_LO * 2) + so, Blo + gb);
    }
    cpa_commit_wait0();
    __syncthreads();

#pragma unroll
    for (int s = 0; s < 4; ++s) {
      const int k0 = s * 16;
      uint32_t ahi[2][4], alo[2][4];
#pragma unroll
      for (int mt = 0; mt < 2; ++mt) {
        uint32_t off = (uint32_t)((wm * 32 + mt * 16 + a_row) * SA + k0 + a_col) * 2;
        ldsm_x4(sbase + OA_HI * 2 + off, ahi[mt]);
        ldsm_x4(sbase + OA_LO * 2 + off, alo[mt]);
      }
#pragma unroll
      for (int nt2 = 0; nt2 < 4; ++nt2) {
        uint32_t bh[4], bl[4];
        uint32_t off = (uint32_t)((wn * 64 + nt2 * 16 + b_row) * SA + k0 + b_col) * 2;
        ldsm_x4(sbase + OB_HI * 2 + off, bh);   // non-trans: [N,K] row-major IS col operand
        ldsm_x4(sbase + OB_LO * 2 + off, bl);
#pragma unroll
        for (int mt = 0; mt < 2; ++mt) {
          mma_bf16(acc[mt][nt2 * 2], ahi[mt], bh);
          mma_bf16(acc[mt][nt2 * 2], ahi[mt], bl);
          mma_bf16(acc[mt][nt2 * 2], alo[mt], bh);
          mma_bf16(acc[mt][nt2 * 2 + 1], ahi[mt], bh + 2);
          mma_bf16(acc[mt][nt2 * 2 + 1], ahi[mt], bl + 2);
          mma_bf16(acc[mt][nt2 * 2 + 1], alo[mt], bh + 2);
        }
      }
    }
  }

  // epilogue: c frag m16n8: rows lane>>2 and +8, cols (lane&3)*2
#pragma unroll
  for (int mt = 0; mt < 2; ++mt) {
    int r0 = m0 + wm * 32 + mt * 16 + (lane >> 2);
#pragma unroll
    for (int nt = 0; nt < 8; ++nt) {
      int col = n0 + wn * 64 + nt * 8 + (lane & 3) * 2;
      float2 v0 = {acc[mt][nt][0], acc[mt][nt][1]};
      float2 v1 = {acc[mt][nt][2], acc[mt][nt][3]};
      *(float2*)(C + (size_t)r0 * N + col) = v0;
      *(float2*)(C + (size_t)(r0 + 8) * N + col) = v1;
    }
  }
}

// ---------------------------------------------------------------------------
// RoPE
// ---------------------------------------------------------------------------
__global__ void rope_kernel(float* __restrict__ t, const float* __restrict__ fcos,
                            const float* __restrict__ fsin, int nheads) {
  int idx = blockIdx.x * blockDim.x + threadIdx.x;
  int total = BATCH * SEQ * nheads * (HD / 2);
  if (idx >= total) return;
  int p = idx & 63;
  int rest = idx >> 6;
  int h = rest % nheads;
  rest /= nheads;
  int s = rest & (SEQ - 1);
  int b = rest >> 11;
  float c = fcos[s * 64 + p];
  float sn = fsin[s * 64 + p];
  float* base = t + ((size_t)(b * SEQ + s) * nheads + h) * HD + p * 2;
  float x0 = base[0], x1 = base[1];
  base[0] = x0 * c - x1 * sn;
  base[1] = x0 * sn + x1 * c;
}

// ---------------------------------------------------------------------------
// Flash attention, fp32, causal (unchanged, known-good)
// ---------------------------------------------------------------------------
#define FAM 64
#define FAN 64
#define QS_STRIDE 132
#define KT_STRIDE 68
#define VS_STRIDE 132
#define SS_STRIDE 65
#define FA_SMEM_FLOATS (FAM * QS_STRIDE + HD * KT_STRIDE + FAN * VS_STRIDE + FAM * SS_STRIDE + 3 * FAM)
#define FA_SMEM_BYTES (FA_SMEM_FLOATS * 4)

__global__ __launch_bounds__(256) void fa_kernel(
    const float* __restrict__ q, const float* __restrict__ k,
    const float* __restrict__ v, float* __restrict__ o) {
  extern __shared__ float sm[];
  float* Qs = sm;
  float* Kt = Qs + FAM * QS_STRIDE;
  float* Vs = Kt + HD * KT_STRIDE;
  float* Ss = Vs + FAN * VS_STRIDE;
  float* m_s = Ss + FAM * SS_STRIDE;
  float* l_s = m_s + FAM;
  float* f_s = l_s + FAM;

  const int tid = threadIdx.x;
  const int m0 = blockIdx.x * FAM;
  const int h = blockIdx.y;
  const int b = blockIdx.z;
  const int g = h >> 2;
  const float scale = 0.08838834764831845f;

  for (int i = tid; i < FAM * (HD / 4); i += 256) {
    int r = i >> 5;
    int cc = (i & 31) * 4;
    float4 vq = *(const float4*)(q + ((size_t)(b * SEQ + m0 + r) * NH + h) * HD + cc);
    vq.x *= scale; vq.y *= scale; vq.z *= scale; vq.w *= scale;
    *(float4*)&Qs[r * QS_STRIDE + cc] = vq;
  }
  if (tid < FAM) {
    m_s[tid] = -1e30f;
    l_s[tid] = 0.f;
  }

  const int tr = tid >> 4;
  const int tc = tid & 15;

  float acc[4][8];
#pragma unroll
  for (int i = 0; i < 4; ++i)
#pragma unroll
    for (int j = 0; j < 8; ++j) acc[i][j] = 0.f;

  const int n_tiles = blockIdx.x + 1;

  for (int t = 0; t < n_tiles; ++t) {
    const int n0 = t * FAN;
    __syncthreads();
    for (int i = tid; i < FAN * (HD / 4); i += 256) {
      int r = i >> 5;
      int cc = (i & 31) * 4;
      const float* kvbase = k + ((size_t)(b * SEQ + n0 + r) * NKV + g) * HD + cc;
      float4 vk = *(const float4*)kvbase;
      Kt[(cc + 0) * KT_STRIDE + r] = vk.x;
      Kt[(cc + 1) * KT_STRIDE + r] = vk.y;
      Kt[(cc + 2) * KT_STRIDE + r] = vk.z;
      Kt[(cc + 3) * KT_STRIDE + r] = vk.w;
      const float* vvbase = v + ((size_t)(b * SEQ + n0 + r) * NKV + g) * HD + cc;
      *(float4*)&Vs[r * VS_STRIDE + cc] = *(const float4*)vvbase;
    }
    __syncthreads();

    float s4[4][4];
#pragma unroll
    for (int i = 0; i < 4; ++i)
#pragma unroll
      for (int j = 0; j < 4; ++j) s4[i][j] = 0.f;

    for (int kk = 0; kk < HD; ++kk) {
      float qv0 = Qs[(tr * 4 + 0) * QS_STRIDE + kk];
      float qv1 = Qs[(tr * 4 + 1) * QS_STRIDE + kk];
      float qv2 = Qs[(tr * 4 + 2) * QS_STRIDE + kk];
      float qv3 = Qs[(tr * 4 + 3) * QS_STRIDE + kk];
      float4 kv = *(const float4*)&Kt[kk * KT_STRIDE + tc * 4];
      s4[0][0] += qv0 * kv.x; s4[0][1] += qv0 * kv.y; s4[0][2] += qv0 * kv.z; s4[0][3] += qv0 * kv.w;
      s4[1][0] += qv1 * kv.x; s4[1][1] += qv1 * kv.y; s4[1][2] += qv1 * kv.z; s4[1][3] += qv1 * kv.w;
      s4[2][0] += qv2 * kv.x; s4[2][1] += qv2 * kv.y; s4[2][2] += qv2 * kv.z; s4[2][3] += qv2 * kv.w;
      s4[3][0] += qv3 * kv.x; s4[3][1] += qv3 * kv.y; s4[3][2] += qv3 * kv.z; s4[3][3] += qv3 * kv.w;
    }
#pragma unroll
    for (int i = 0; i < 4; ++i) {
      int srow = m0 + tr * 4 + i;
#pragma unroll
      for (int j = 0; j < 4; ++j) {
        int scol = n0 + tc * 4 + j;
        float val = s4[i][j] + ((scol > srow) ? NEG_INF_F : 0.f);
        Ss[(tr * 4 + i) * SS_STRIDE + tc * 4 + j] = val;
      }
    }
    __syncthreads();

    if (tid < FAM) {
      float mx = -1e30f;
      for (int c = 0; c < FAN; ++c) mx = fmaxf(mx, Ss[tid * SS_STRIDE + c]);
      float mold = m_s[tid];
      float mnew = fmaxf(mold, mx);
      float f = __expf(mold - mnew);
      m_s[tid] = mnew;
      f_s[tid] = f;
      l_s[tid] *= f;
    }
    __syncthreads();

#pragma unroll
    for (int i = 0; i < 4; ++i) {
      int r = tr * 4 + i;
      float mnew = m_s[r];
#pragma unroll
      for (int j = 0; j < 4; ++j) {
        float* p = &Ss[r * SS_STRIDE + tc * 4 + j];
        *p = __expf(*p - mnew);
      }
    }
#pragma unroll
    for (int i = 0; i < 4; ++i) {
      float f = f_s[tr * 4 + i];
#pragma unroll
      for (int j = 0; j < 8; ++j) acc[i][j] *= f;
    }
    __syncthreads();

    if (tid < FAM) {
      float s = 0.f;
      for (int c = 0; c < FAN; ++c) s += Ss[tid * SS_STRIDE + c];
      l_s[tid] += s;
    }

    for (int kk = 0; kk < FAN; ++kk) {
      float p0 = Ss[(tr * 4 + 0) * SS_STRIDE + kk];
      float p1 = Ss[(tr * 4 + 1) * SS_STRIDE + kk];
      float p2 = Ss[(tr * 4 + 2) * SS_STRIDE + kk];
      float p3 = Ss[(tr * 4 + 3) * SS_STRIDE + kk];
      float4 v0 = *(const float4*)&Vs[kk * VS_STRIDE + tc * 8];
      float4 v1 = *(const float4*)&Vs[kk * VS_STRIDE + tc * 8 + 4];
      acc[0][0] += p0 * v0.x; acc[0][1] += p0 * v0.y; acc[0][2] += p0 * v0.z; acc[0][3] += p0 * v0.w;
      acc[0][4] += p0 * v1.x; acc[0][5] += p0 * v1.y; acc[0][6] += p0 * v1.z; acc[0][7] += p0 * v1.w;
      acc[1][0] += p1 * v0.x; acc[1][1] += p1 * v0.y; acc[1][2] += p1 * v0.z; acc[1][3] += p1 * v0.w;
      acc[1][4] += p1 * v1.x; acc[1][5] += p1 * v1.y; acc[1][6] += p1 * v1.z; acc[1][7] += p1 * v1.w;
      acc[2][0] += p2 * v0.x; acc[2][1] += p2 * v0.y; acc[2][2] += p2 * v0.z; acc[2][3] += p2 * v0.w;
      acc[2][4] += p2 * v1.x; acc[2][5] += p2 * v1.y; acc[2][6] += p2 * v1.z; acc[2][7] += p2 * v1.w;
      acc[3][0] += p3 * v0.x; acc[3][1] += p3 * v0.y; acc[3][2] += p3 * v0.z; acc[3][3] += p3 * v0.w;
      acc[3][4] += p3 * v1.x; acc[3][5] += p3 * v1.y; acc[3][6] += p3 * v1.z; acc[3][7] += p3 * v1.w;
    }
  }
  __syncthreads();

#pragma unroll
  for (int i = 0; i < 4; ++i) {
    int r = tr * 4 + i;
    float inv = 1.f / l_s[r];
    float* orow = o + ((size_t)(b * SEQ + m0 + r) * NH + h) * HD + tc * 8;
    float4 o0 = {acc[i][0] * inv, acc[i][1] * inv, acc[i][2] * inv, acc[i][3] * inv};
    float4 o1 = {acc[i][4] * inv, acc[i][5] * inv, acc[i][6] * inv, acc[i][7] * inv};
    *(float4*)(orow) = o0;
    *(float4*)(orow + 4) = o1;
  }
}

// ---------------------------------------------------------------------------
// Launch
// ---------------------------------------------------------------------------
extern "C" void kernel_launch(void* const* d_in, const int* in_sizes, int n_in,
                              void* d_out, int out_size) {
  const float* x    = (const float*)d_in[0];
  const float* fcos = (const float*)d_in[1];
  const float* fsin = (const float*)d_in[2];
  // d_in[3] = mask (causal mask applied analytically)
  const float* wq = (const float*)d_in[4];
  const float* wk = (const float*)d_in[5];
  const float* wv = (const float*)d_in[6];
  const float* wo = (const float*)d_in[7];
  float* out = (float*)d_out;

  float *q, *k, *v, *ao;
  cudaGetSymbolAddress((void**)&q, g_q);
  cudaGetSymbolAddress((void**)&k, g_k);
  cudaGetSymbolAddress((void**)&v, g_v);
  cudaGetSymbolAddress((void**)&ao, g_ao);
  __nv_bfloat16 *xh, *xl, *aoh, *aol, *wqh, *wql, *wkh, *wkl, *wvh, *wvl, *woh, *wol;
  cudaGetSymbolAddress((void**)&xh, g_x_hi);
  cudaGetSymbolAddress((void**)&xl, g_x_lo);
  cudaGetSymbolAddress((void**)&aoh, g_ao_hi);
  cudaGetSymbolAddress((void**)&aol, g_ao_lo);
  cudaGetSymbolAddress((void**)&wqh, g_wq_hi);
  cudaGetSymbolAddress((void**)&wql, g_wq_lo);
  cudaGetSymbolAddress((void**)&wkh, g_wk_hi);
  cudaGetSymbolAddress((void**)&wkl, g_wk_lo);
  cudaGetSymbolAddress((void**)&wvh, g_wv_hi);
  cudaGetSymbolAddress((void**)&wvl, g_wv_lo);
  cudaGetSymbolAddress((void**)&woh, g_wo_hi);
  cudaGetSymbolAddress((void**)&wol, g_wo_lo);

  static bool attr_done = false;
  if (!attr_done) {
    cudaFuncSetAttribute(gemm_mma_kernel,
                         cudaFuncAttributeMaxDynamicSharedMemorySize, GEMM_SMEM);
    cudaFuncSetAttribute(fa_kernel, cudaFuncAttributeMaxDynamicSharedMemorySize,
                         FA_SMEM_BYTES);
    attr_done = true;
  }

  // split inputs / transpose+split weights
  {
    int nx = MTOK * DMODEL;
    split_kernel<<<(nx + 255) / 256, 256>>>(x, xh, xl, nx);
    dim3 blk(32, 8);
    transpose_split_kernel<<<dim3(DMODEL / 32, DMODEL / 32), blk>>>(wq, wqh, wql, DMODEL, DMODEL);
    transpose_split_kernel<<<dim3(KVDIM / 32, DMODEL / 32), blk>>>(wk, wkh, wkl, DMODEL, KVDIM);
    transpose_split_kernel<<<dim3(KVDIM / 32, DMODEL / 32), blk>>>(wv, wvh, wvl, DMODEL, KVDIM);
    transpose_split_kernel<<<dim3(DMODEL / 32, DMODEL / 32), blk>>>(wo, woh, wol, DMODEL, DMODEL);
  }

  // projections on tensor cores (mma.sync)
  gemm_mma_kernel<<<dim3(DMODEL / 128, MTOK / 128), 256, GEMM_SMEM>>>(
      xh, xl, wqh, wql, q, MTOK, DMODEL, DMODEL);
  gemm_mma_kernel<<<dim3(KVDIM / 128, MTOK / 128), 256, GEMM_SMEM>>>(
      xh, xl, wkh, wkl, k, MTOK, KVDIM, DMODEL);
  gemm_mma_kernel<<<dim3(KVDIM / 128, MTOK / 128), 256, GEMM_SMEM>>>(
      xh, xl, wvh, wvl, v, MTOK, KVDIM, DMODEL);

  // RoPE
  {
    int tq = BATCH * SEQ * NH * (HD / 2);
    rope_kernel<<<(tq + 255) / 256, 256>>>(q, fcos, fsin, NH);
    int tk = BATCH * SEQ * NKV * (HD / 2);
    rope_kernel<<<(tk + 255) / 256, 256>>>(k, fcos, fsin, NKV);
  }

  // Flash attention (fp32)
  fa_kernel<<<dim3(SEQ / FAM, NH, BATCH), 256, FA_SMEM_BYTES>>>(q, k, v, ao);

  // Output projection on tensor cores
  {
    int na = MTOK * DMODEL;
    split_kernel<<<(na + 255) / 256, 256>>>(ao, aoh, aol, na);
  }
  gemm_mma_kernel<<<dim3(DMODEL / 128, MTOK / 128), 256, GEMM_SMEM>>>(
      aoh, aol, woh, wol, out, MTOK, DMODEL, DMODEL);
}

// round 5
// speedup vs baseline: 3.3273x; 2.0574x over previous
#include <cuda_runtime.h>
#include <cuda_bf16.h>
#include <cstdint>
#include <math.h>

// Problem dims (fixed by reference)
#define BATCH 2
#define SEQ 2048
#define DMODEL 2048
#define NH 16
#define NKV 4
#define HD 128
#define MTOK (BATCH * SEQ)          // 4096 tokens
#define KVDIM (NKV * HD)            // 512

// ---------------------------------------------------------------------------
// Scratch (device globals; runtime allocation is forbidden)
// ---------------------------------------------------------------------------
__device__ float g_q[MTOK * NH * HD];
__device__ float g_k[MTOK * KVDIM];
__device__ float g_v[MTOK * KVDIM];
__device__ float g_ao[MTOK * NH * HD];

// split-precision bf16 operands
__device__ __nv_bfloat16 g_x_hi[MTOK * DMODEL];
__device__ __nv_bfloat16 g_x_lo[MTOK * DMODEL];
__device__ __nv_bfloat16 g_ao_hi[MTOK * DMODEL];
__device__ __nv_bfloat16 g_ao_lo[MTOK * DMODEL];
// weights transposed to [N, K]
__device__ __nv_bfloat16 g_wq_hi[DMODEL * DMODEL];
__device__ __nv_bfloat16 g_wq_lo[DMODEL * DMODEL];
__device__ __nv_bfloat16 g_wk_hi[KVDIM * DMODEL];
__device__ __nv_bfloat16 g_wk_lo[KVDIM * DMODEL];
__device__ __nv_bfloat16 g_wv_hi[KVDIM * DMODEL];
__device__ __nv_bfloat16 g_wv_lo[KVDIM * DMODEL];
__device__ __nv_bfloat16 g_wo_hi[DMODEL * DMODEL];
__device__ __nv_bfloat16 g_wo_lo[DMODEL * DMODEL];

// ---------------------------------------------------------------------------
// helpers
// ---------------------------------------------------------------------------
__device__ __forceinline__ uint32_t smem_u32(const void* p) {
  uint32_t a;
  asm("{ .reg .u64 t; cvta.to.shared.u64 t, %1; cvt.u32.u64 %0, t; }"
      : "=r"(a) : "l"(p));
  return a;
}
__device__ __forceinline__ void cpa16(uint32_t s, const void* g) {
  asm volatile("cp.async.cg.shared.global [%0], [%1], 16;"
               :: "r"(s), "l"(g) : "memory");
}
__device__ __forceinline__ void cpa_commit_wait0() {
  asm volatile("cp.async.commit_group;" ::: "memory");
  asm volatile("cp.async.wait_group 0;" ::: "memory");
}
__device__ __forceinline__ void ldsm_x4(uint32_t addr, uint32_t* r) {
  asm volatile("ldmatrix.sync.aligned.m8n8.x4.shared.b16 {%0,%1,%2,%3}, [%4];"
               : "=r"(r[0]), "=r"(r[1]), "=r"(r[2]), "=r"(r[3]) : "r"(addr));
}
__device__ __forceinline__ void ldsm_x4_t(uint32_t addr, uint32_t* r) {
  asm volatile("ldmatrix.sync.aligned.m8n8.x4.trans.shared.b16 {%0,%1,%2,%3}, [%4];"
               : "=r"(r[0]), "=r"(r[1]), "=r"(r[2]), "=r"(r[3]) : "r"(addr));
}
__device__ __forceinline__ void mma_bf16(float* d, const uint32_t* a,
                                         const uint32_t* b) {
  asm volatile(
      "mma.sync.aligned.m16n8k16.row.col.f32.bf16.bf16.f32 "
      "{%0,%1,%2,%3}, {%4,%5,%6,%7}, {%8,%9}, {%0,%1,%2,%3};"
      : "+f"(d[0]), "+f"(d[1]), "+f"(d[2]), "+f"(d[3])
      : "r"(a[0]), "r"(a[1]), "r"(a[2]), "r"(a[3]), "r"(b[0]), "r"(b[1]));
}
// pack: lo 16 bits = bf16(a), hi = bf16(b)
__device__ __forceinline__ uint32_t pack_bf16(float a, float b) {
  uint32_t r;
  asm("cvt.rn.bf16x2.f32 %0, %1, %2;" : "=r"(r) : "f"(b), "f"(a));
  return r;
}
__device__ __forceinline__ float bf16_round(float f) {
  return __bfloat162float(__float2bfloat16(f));
}

// ---------------------------------------------------------------------------
// Split-precision conversion kernels
// ---------------------------------------------------------------------------
__global__ void split_kernel(const float* __restrict__ src,
                             __nv_bfloat16* __restrict__ hi,
                             __nv_bfloat16* __restrict__ lo, int n) {
  int i = blockIdx.x * blockDim.x + threadIdx.x;
  if (i >= n) return;
  float f = src[i];
  __nv_bfloat16 h = __float2bfloat16(f);
  hi[i] = h;
  lo[i] = __float2bfloat16(f - __bfloat162float(h));
}

// w[K,N] fp32 -> th/tl [N,K] bf16 (transpose + split)
__global__ void transpose_split_kernel(const float* __restrict__ w,
                                       __nv_bfloat16* __restrict__ th,
                                       __nv_bfloat16* __restrict__ tl,
                                       int K, int N) {
  __shared__ float tile[32][33];
  int nx = blockIdx.x * 32 + threadIdx.x;
  int k0 = blockIdx.y * 32;
  for (int i = threadIdx.y; i < 32; i += 8)
    tile[i][threadIdx.x] = w[(size_t)(k0 + i) * N + nx];
  __syncthreads();
  for (int j = threadIdx.y; j < 32; j += 8) {
    int n = blockIdx.x * 32 + j;
    int kk = k0 + threadIdx.x;
    float f = tile[threadIdx.x][j];
    __nv_bfloat16 h = __float2bfloat16(f);
    th[(size_t)n * K + kk] = h;
    tl[(size_t)n * K + kk] = __float2bfloat16(f - __bfloat162float(h));
  }
}

// ---------------------------------------------------------------------------
// mma.sync bf16 split-precision GEMM: C[M,N] = A[M,K] @ Bt[N,K]^T
// ---------------------------------------------------------------------------
#define SA 72
#define TILE_E (128 * SA)
#define GEMM_SMEM (4 * TILE_E * 2)

__global__ __launch_bounds__(256, 2) void gemm_mma_kernel(
    const __nv_bfloat16* __restrict__ Ahi, const __nv_bfloat16* __restrict__ Alo,
    const __nv_bfloat16* __restrict__ Bhi, const __nv_bfloat16* __restrict__ Blo,
    float* __restrict__ C, int M, int N, int K) {
  extern __shared__ __nv_bfloat16 smb[];
  const int tid = threadIdx.x;
  const int lane = tid & 31;
  const int wid = tid >> 5;
  const int wm = wid & 3;
  const int wn = wid >> 2;
  const int m0 = blockIdx.y * 128;
  const int n0 = blockIdx.x * 128;
  const uint32_t sbase = smem_u32(smb);

  const uint32_t OA_HI = 0, OA_LO = TILE_E, OB_HI = 2 * TILE_E, OB_LO = 3 * TILE_E;

  float acc[2][8][4];
#pragma unroll
  for (int i = 0; i < 2; ++i)
#pragma unroll
    for (int j = 0; j < 8; ++j)
#pragma unroll
      for (int q = 0; q < 4; ++q) acc[i][j][q] = 0.f;

  const int a_row = lane & 15;
  const int a_col = (lane >> 4) * 8;
  const int b_row = (lane & 7) + ((lane & 16) >> 1);
  const int b_col = lane & 8;

  const int l_r = tid >> 3;
  const int l_c = (tid & 7) * 8;

  const int nchunks = K >> 6;
  for (int c = 0; c < nchunks; ++c) {
    const int k0g = c << 6;
    if (c) __syncthreads();
#pragma unroll
    for (int q = 0; q < 4; ++q) {
      int r = l_r + q * 32;
      const size_t ga = (size_t)(m0 + r) * K + k0g + l_c;
      const size_t gb = (size_t)(n0 + r) * K + k0g + l_c;
      uint32_t so = (uint32_t)(r * SA + l_c) * 2;
      cpa16(sbase + (OA_HI * 2) + so, Ahi + ga);
      cpa16(sbase + (OA_LO * 2) + so, Alo + ga);
      cpa16(sbase + (OB_HI * 2) + so, Bhi + gb);
      cpa16(sbase + (OB_LO * 2) + so, Blo + gb);
    }
    cpa_commit_wait0();
    __syncthreads();

#pragma unroll
    for (int s = 0; s < 4; ++s) {
      const int k0 = s * 16;
      uint32_t ahi[2][4], alo[2][4];
#pragma unroll
      for (int mt = 0; mt < 2; ++mt) {
        uint32_t off = (uint32_t)((wm * 32 + mt * 16 + a_row) * SA + k0 + a_col) * 2;
        ldsm_x4(sbase + OA_HI * 2 + off, ahi[mt]);
        ldsm_x4(sbase + OA_LO * 2 + off, alo[mt]);
      }
#pragma unroll
      for (int nt2 = 0; nt2 < 4; ++nt2) {
        uint32_t bh[4], bl[4];
        uint32_t off = (uint32_t)((wn * 64 + nt2 * 16 + b_row) * SA + k0 + b_col) * 2;
        ldsm_x4(sbase + OB_HI * 2 + off, bh);
        ldsm_x4(sbase + OB_LO * 2 + off, bl);
#pragma unroll
        for (int mt = 0; mt < 2; ++mt) {
          mma_bf16(acc[mt][nt2 * 2], ahi[mt], bh);
          mma_bf16(acc[mt][nt2 * 2], ahi[mt], bl);
          mma_bf16(acc[mt][nt2 * 2], alo[mt], bh);
          mma_bf16(acc[mt][nt2 * 2 + 1], ahi[mt], bh + 2);
          mma_bf16(acc[mt][nt2 * 2 + 1], ahi[mt], bl + 2);
          mma_bf16(acc[mt][nt2 * 2 + 1], alo[mt], bh + 2);
        }
      }
    }
  }

#pragma unroll
  for (int mt = 0; mt < 2; ++mt) {
    int r0 = m0 + wm * 32 + mt * 16 + (lane >> 2);
#pragma unroll
    for (int nt = 0; nt < 8; ++nt) {
      int col = n0 + wn * 64 + nt * 8 + (lane & 3) * 2;
      float2 v0 = {acc[mt][nt][0], acc[mt][nt][1]};
      float2 v1 = {acc[mt][nt][2], acc[mt][nt][3]};
      *(float2*)(C + (size_t)r0 * N + col) = v0;
      *(float2*)(C + (size_t)(r0 + 8) * N + col) = v1;
    }
  }
}

// ---------------------------------------------------------------------------
// RoPE
// ---------------------------------------------------------------------------
__global__ void rope_kernel(float* __restrict__ t, const float* __restrict__ fcos,
                            const float* __restrict__ fsin, int nheads) {
  int idx = blockIdx.x * blockDim.x + threadIdx.x;
  int total = BATCH * SEQ * nheads * (HD / 2);
  if (idx >= total) return;
  int p = idx & 63;
  int rest = idx >> 6;
  int h = rest % nheads;
  rest /= nheads;
  int s = rest & (SEQ - 1);
  int b = rest >> 11;
  float c = fcos[s * 64 + p];
  float sn = fsin[s * 64 + p];
  float* base = t + ((size_t)(b * SEQ + s) * nheads + h) * HD + p * 2;
  float x0 = base[0], x1 = base[1];
  base[0] = x0 * c - x1 * sn;
  base[1] = x0 * sn + x1 * c;
}

// ---------------------------------------------------------------------------
// Tensor-core flash attention, split-precision bf16, causal.
// BLOCK_M=64 (4 warps x m16), BLOCK_N=64, D=128.
// ---------------------------------------------------------------------------
#define FSD 136                       // smem stride (elements)
#define FTE (64 * FSD)                // elements per tile
#define FA_SMEM (6 * FTE * 2)         // Qhi,Qlo,Khi,Klo,Vhi,Vlo = 104448 B

__global__ __launch_bounds__(128) void fa_mma_kernel(
    const float* __restrict__ q, const float* __restrict__ k,
    const float* __restrict__ v, float* __restrict__ o) {
  extern __shared__ __nv_bfloat16 fsm[];
  const uint32_t sbase = smem_u32(fsm);
  const int tid = threadIdx.x;
  const int lane = tid & 31;
  const int w = tid >> 5;

  const int mt = gridDim.x - 1 - blockIdx.x;   // heavy tiles first
  const int m0 = mt * 64;
  const int h = blockIdx.y;
  const int b = blockIdx.z;
  const int g = h >> 2;
  const float scale = 0.08838834764831845f;    // 1/sqrt(128)

  // element offsets
  const uint32_t QH = 0, QL = FTE, KH = 2 * FTE, KL = 3 * FTE, VH = 4 * FTE,
                 VL = 5 * FTE;

  // --- load Q tile (scaled, split) ---
#pragma unroll
  for (int it = 0; it < 16; ++it) {
    int i = tid + it * 128;
    int r = i >> 5;
    int cc = (i & 31) * 4;
    float4 f = *(const float4*)(q + ((size_t)(b * SEQ + m0 + r) * NH + h) * HD + cc);
    f.x *= scale; f.y *= scale; f.z *= scale; f.w *= scale;
    uint32_t e = r * FSD + cc;
    uint2 hv = {pack_bf16(f.x, f.y), pack_bf16(f.z, f.w)};
    uint2 lv = {pack_bf16(f.x - bf16_round(f.x), f.y - bf16_round(f.y)),
                pack_bf16(f.z - bf16_round(f.z), f.w - bf16_round(f.w))};
    *(uint2*)((char*)fsm + (size_t)(QH + e) * 2) = hv;
    *(uint2*)((char*)fsm + (size_t)(QL + e) * 2) = lv;
  }

  // per-lane state: rows r_lo = lane>>2, r_hi = +8 within warp strip
  float m_lo = -1e30f, m_hi = -1e30f, l_lo = 0.f, l_hi = 0.f;
  float oacc[16][4];
#pragma unroll
  for (int i = 0; i < 16; ++i)
#pragma unroll
    for (int j = 0; j < 4; ++j) oacc[i][j] = 0.f;

  const int a_row = lane & 15;
  const int a_col = (lane >> 4) * 8;
  const int b_row = (lane & 7) + ((lane & 16) >> 1);
  const int b_col = lane & 8;

  for (int t = 0; t <= mt; ++t) {
    const int n0 = t * 64;
    __syncthreads();
    // --- load K,V tile (split) ---
#pragma unroll
    for (int it = 0; it < 16; ++it) {
      int i = tid + it * 128;
      int r = i >> 5;
      int cc = (i & 31) * 4;
      uint32_t e = r * FSD + cc;
      const size_t gi = ((size_t)(b * SEQ + n0 + r) * NKV + g) * HD + cc;
      float4 fk = *(const float4*)(k + gi);
      *(uint2*)((char*)fsm + (size_t)(KH + e) * 2) =
          make_uint2(pack_bf16(fk.x, fk.y), pack_bf16(fk.z, fk.w));
      *(uint2*)((char*)fsm + (size_t)(KL + e) * 2) =
          make_uint2(pack_bf16(fk.x - bf16_round(fk.x), fk.y - bf16_round(fk.y)),
                     pack_bf16(fk.z - bf16_round(fk.z), fk.w - bf16_round(fk.w)));
      float4 fv = *(const float4*)(v + gi);
      *(uint2*)((char*)fsm + (size_t)(VH + e) * 2) =
          make_uint2(pack_bf16(fv.x, fv.y), pack_bf16(fv.z, fv.w));
      *(uint2*)((char*)fsm + (size_t)(VL + e) * 2) =
          make_uint2(pack_bf16(fv.x - bf16_round(fv.x), fv.y - bf16_round(fv.y)),
                     pack_bf16(fv.z - bf16_round(fv.z), fv.w - bf16_round(fv.w)));
    }
    __syncthreads();

    // --- S = Q @ K^T (split 3-product) ---
    float sacc[8][4];
#pragma unroll
    for (int i = 0; i < 8; ++i)
#pragma unroll
      for (int j = 0; j < 4; ++j) sacc[i][j] = 0.f;

#pragma unroll
    for (int kc = 0; kc < 8; ++kc) {
      uint32_t aq_off = (uint32_t)((w * 16 + a_row) * FSD + kc * 16 + a_col) * 2;
      uint32_t aqh[4], aql[4];
      ldsm_x4(sbase + QH * 2 + aq_off, aqh);
      ldsm_x4(sbase + QL * 2 + aq_off, aql);
#pragma unroll
      for (int np = 0; np < 4; ++np) {
        uint32_t bo = (uint32_t)((np * 16 + b_row) * FSD + kc * 16 + b_col) * 2;
        uint32_t bh[4], bl[4];
        ldsm_x4(sbase + KH * 2 + bo, bh);
        ldsm_x4(sbase + KL * 2 + bo, bl);
        mma_bf16(sacc[np * 2], aqh, bh);
        mma_bf16(sacc[np * 2], aqh, bl);
        mma_bf16(sacc[np * 2], aql, bh);
        mma_bf16(sacc[np * 2 + 1], aqh, bh + 2);
        mma_bf16(sacc[np * 2 + 1], aqh, bl + 2);
        mma_bf16(sacc[np * 2 + 1], aql, bh + 2);
      }
    }

    // --- causal mask (diagonal tile only) ---
    if (t == mt) {
      int row_lo = w * 16 + (lane >> 2);
      int row_hi = row_lo + 8;
#pragma unroll
      for (int nt = 0; nt < 8; ++nt) {
        int c0 = nt * 8 + (lane & 3) * 2;
        if (c0 > row_lo) sacc[nt][0] = -1e30f;
        if (c0 + 1 > row_lo) sacc[nt][1] = -1e30f;
        if (c0 > row_hi) sacc[nt][2] = -1e30f;
        if (c0 + 1 > row_hi) sacc[nt][3] = -1e30f;
      }
    }

    // --- online softmax ---
    float rmax_lo = -1e30f, rmax_hi = -1e30f;
#pragma unroll
    for (int nt = 0; nt < 8; ++nt) {
      rmax_lo = fmaxf(rmax_lo, fmaxf(sacc[nt][0], sacc[nt][1]));
      rmax_hi = fmaxf(rmax_hi, fmaxf(sacc[nt][2], sacc[nt][3]));
    }
#pragma unroll
    for (int d = 1; d < 4; d <<= 1) {
      rmax_lo = fmaxf(rmax_lo, __shfl_xor_sync(0xffffffffu, rmax_lo, d));
      rmax_hi = fmaxf(rmax_hi, __shfl_xor_sync(0xffffffffu, rmax_hi, d));
    }
    float mn_lo = fmaxf(m_lo, rmax_lo);
    float mn_hi = fmaxf(m_hi, rmax_hi);
    float f_lo = __expf(m_lo - mn_lo);
    float f_hi = __expf(m_hi - mn_hi);
    m_lo = mn_lo; m_hi = mn_hi;

    float rsum_lo = 0.f, rsum_hi = 0.f;
#pragma unroll
    for (int nt = 0; nt < 8; ++nt) {
      sacc[nt][0] = __expf(sacc[nt][0] - mn_lo);
      sacc[nt][1] = __expf(sacc[nt][1] - mn_lo);
      sacc[nt][2] = __expf(sacc[nt][2] - mn_hi);
      sacc[nt][3] = __expf(sacc[nt][3] - mn_hi);
      rsum_lo += sacc[nt][0] + sacc[nt][1];
      rsum_hi += sacc[nt][2] + sacc[nt][3];
    }
#pragma unroll
    for (int d = 1; d < 4; d <<= 1) {
      rsum_lo += __shfl_xor_sync(0xffffffffu, rsum_lo, d);
      rsum_hi += __shfl_xor_sync(0xffffffffu, rsum_hi, d);
    }
    l_lo = l_lo * f_lo + rsum_lo;
    l_hi = l_hi * f_hi + rsum_hi;
#pragma unroll
    for (int i = 0; i < 16; ++i) {
      oacc[i][0] *= f_lo; oacc[i][1] *= f_lo;
      oacc[i][2] *= f_hi; oacc[i][3] *= f_hi;
    }

    // --- O += P @ V (split 3-product; P frags from registers) ---
#pragma unroll
    for (int kt = 0; kt < 4; ++kt) {
      const float* s0 = sacc[2 * kt];
      const float* s1 = sacc[2 * kt + 1];
      uint32_t ph[4], pl[4];
      ph[0] = pack_bf16(s0[0], s0[1]);
      ph[1] = pack_bf16(s0[2], s0[3]);
      ph[2] = pack_bf16(s1[0], s1[1]);
      ph[3] = pack_bf16(s1[2], s1[3]);
      pl[0] = pack_bf16(s0[0] - bf16_round(s0[0]), s0[1] - bf16_round(s0[1]));
      pl[1] = pack_bf16(s0[2] - bf16_round(s0[2]), s0[3] - bf16_round(s0[3]));
      pl[2] = pack_bf16(s1[0] - bf16_round(s1[0]), s1[1] - bf16_round(s1[1]));
      pl[3] = pack_bf16(s1[2] - bf16_round(s1[2]), s1[3] - bf16_round(s1[3]));
#pragma unroll
      for (int dp = 0; dp < 8; ++dp) {
        uint32_t vo = (uint32_t)((kt * 16 + (lane & 15)) * FSD + dp * 16 +
                                 ((lane >> 4) << 3)) * 2;
        uint32_t vh[4], vl[4];
        ldsm_x4_t(sbase + VH * 2 + vo, vh);
        ldsm_x4_t(sbase + VL * 2 + vo, vl);
        mma_bf16(oacc[dp * 2], ph, vh);
        mma_bf16(oacc[dp * 2], pl, vh);
        mma_bf16(oacc[dp * 2], ph, vl);
        mma_bf16(oacc[dp * 2 + 1], ph, vh + 2);
        mma_bf16(oacc[dp * 2 + 1], pl, vh + 2);
        mma_bf16(oacc[dp * 2 + 1], ph, vl + 2);
      }
    }
  }

  // --- epilogue: normalize, write [b,s,h,d] ---
  float inv_lo = 1.f / l_lo;
  float inv_hi = 1.f / l_hi;
  int r_lo = m0 + w * 16 + (lane >> 2);
  int r_hi = r_lo + 8;
#pragma unroll
  for (int dt = 0; dt < 16; ++dt) {
    int col = dt * 8 + (lane & 3) * 2;
    float2 v0 = {oacc[dt][0] * inv_lo, oacc[dt][1] * inv_lo};
    float2 v1 = {oacc[dt][2] * inv_hi, oacc[dt][3] * inv_hi};
    *(float2*)(o + ((size_t)(b * SEQ + r_lo) * NH + h) * HD + col) = v0;
    *(float2*)(o + ((size_t)(b * SEQ + r_hi) * NH + h) * HD + col) = v1;
  }
}

// ---------------------------------------------------------------------------
// Launch
// ---------------------------------------------------------------------------
extern "C" void kernel_launch(void* const* d_in, const int* in_sizes, int n_in,
                              void* d_out, int out_size) {
  const float* x    = (const float*)d_in[0];
  const float* fcos = (const float*)d_in[1];
  const float* fsin = (const float*)d_in[2];
  // d_in[3] = mask (causal mask applied analytically)
  const float* wq = (const float*)d_in[4];
  const float* wk = (const float*)d_in[5];
  const float* wv = (const float*)d_in[6];
  const float* wo = (const float*)d_in[7];
  float* out = (float*)d_out;

  float *q, *k, *v, *ao;
  cudaGetSymbolAddress((void**)&q, g_q);
  cudaGetSymbolAddress((void**)&k, g_k);
  cudaGetSymbolAddress((void**)&v, g_v);
  cudaGetSymbolAddress((void**)&ao, g_ao);
  __nv_bfloat16 *xh, *xl, *aoh, *aol, *wqh, *wql, *wkh, *wkl, *wvh, *wvl, *woh, *wol;
  cudaGetSymbolAddress((void**)&xh, g_x_hi);
  cudaGetSymbolAddress((void**)&xl, g_x_lo);
  cudaGetSymbolAddress((void**)&aoh, g_ao_hi);
  cudaGetSymbolAddress((void**)&aol, g_ao_lo);
  cudaGetSymbolAddress((void**)&wqh, g_wq_hi);
  cudaGetSymbolAddress((void**)&wql, g_wq_lo);
  cudaGetSymbolAddress((void**)&wkh, g_wk_hi);
  cudaGetSymbolAddress((void**)&wkl, g_wk_lo);
  cudaGetSymbolAddress((void**)&wvh, g_wv_hi);
  cudaGetSymbolAddress((void**)&wvl, g_wv_lo);
  cudaGetSymbolAddress((void**)&woh, g_wo_hi);
  cudaGetSymbolAddress((void**)&wol, g_wo_lo);

  static bool attr_done = false;
  if (!attr_done) {
    cudaFuncSetAttribute(gemm_mma_kernel,
                         cudaFuncAttributeMaxDynamicSharedMemorySize, GEMM_SMEM);
    cudaFuncSetAttribute(fa_mma_kernel,
                         cudaFuncAttributeMaxDynamicSharedMemorySize, FA_SMEM);
    attr_done = true;
  }

  // split inputs / transpose+split weights
  {
    int nx = MTOK * DMODEL;
    split_kernel<<<(nx + 255) / 256, 256>>>(x, xh, xl, nx);
    dim3 blk(32, 8);
    transpose_split_kernel<<<dim3(DMODEL / 32, DMODEL / 32), blk>>>(wq, wqh, wql, DMODEL, DMODEL);
    transpose_split_kernel<<<dim3(KVDIM / 32, DMODEL / 32), blk>>>(wk, wkh, wkl, DMODEL, KVDIM);
    transpose_split_kernel<<<dim3(KVDIM / 32, DMODEL / 32), blk>>>(wv, wvh, wvl, DMODEL, KVDIM);
    transpose_split_kernel<<<dim3(DMODEL / 32, DMODEL / 32), blk>>>(wo, woh, wol, DMODEL, DMODEL);
  }

  // projections on tensor cores
  gemm_mma_kernel<<<dim3(DMODEL / 128, MTOK / 128), 256, GEMM_SMEM>>>(
      xh, xl, wqh, wql, q, MTOK, DMODEL, DMODEL);
  gemm_mma_kernel<<<dim3(KVDIM / 128, MTOK / 128), 256, GEMM_SMEM>>>(
      xh, xl, wkh, wkl, k, MTOK, KVDIM, DMODEL);
  gemm_mma_kernel<<<dim3(KVDIM / 128, MTOK / 128), 256, GEMM_SMEM>>>(
      xh, xl, wvh, wvl, v, MTOK, KVDIM, DMODEL);

  // RoPE
  {
    int tq = BATCH * SEQ * NH * (HD / 2);
    rope_kernel<<<(tq + 255) / 256, 256>>>(q, fcos, fsin, NH);
    int tk = BATCH * SEQ * NKV * (HD / 2);
    rope_kernel<<<(tk + 255) / 256, 256>>>(k, fcos, fsin, NKV);
  }

  // Tensor-core flash attention
  fa_mma_kernel<<<dim3(SEQ / 64, NH, BATCH), 128, FA_SMEM>>>(q, k, v, ao);

  // Output projection on tensor cores
  {
    int na = MTOK * DMODEL;
    split_kernel<<<(na + 255) / 256, 256>>>(ao, aoh, aol, na);
  }
  gemm_mma_kernel<<<dim3(DMODEL / 128, MTOK / 128), 256, GEMM_SMEM>>>(
      aoh, aol, woh, wol, out, MTOK, DMODEL, DMODEL);
}

// round 6
// speedup vs baseline: 3.3400x; 1.0038x over previous
#include <cuda_runtime.h>
#include <cuda_bf16.h>
#include <cstdint>
#include <math.h>

// Problem dims (fixed by reference)
#define BATCH 2
#define SEQ 2048
#define DMODEL 2048
#define NH 16
#define NKV 4
#define HD 128
#define MTOK (BATCH * SEQ)          // 4096 tokens
#define KVDIM (NKV * HD)            // 512

// ---------------------------------------------------------------------------
// Scratch (device globals; runtime allocation is forbidden)
// ---------------------------------------------------------------------------
__device__ float g_q[MTOK * NH * HD];
__device__ float g_k[MTOK * KVDIM];
__device__ float g_v[MTOK * KVDIM];

// split-precision bf16 operands
__device__ __nv_bfloat16 g_x_hi[MTOK * DMODEL];
__device__ __nv_bfloat16 g_x_lo[MTOK * DMODEL];
__device__ __nv_bfloat16 g_ao_hi[MTOK * DMODEL];
__device__ __nv_bfloat16 g_ao_lo[MTOK * DMODEL];
// weights transposed to [N, K]
__device__ __nv_bfloat16 g_wq_hi[DMODEL * DMODEL];
__device__ __nv_bfloat16 g_wq_lo[DMODEL * DMODEL];
__device__ __nv_bfloat16 g_wk_hi[KVDIM * DMODEL];
__device__ __nv_bfloat16 g_wk_lo[KVDIM * DMODEL];
__device__ __nv_bfloat16 g_wv_hi[KVDIM * DMODEL];
__device__ __nv_bfloat16 g_wv_lo[KVDIM * DMODEL];
__device__ __nv_bfloat16 g_wo_hi[DMODEL * DMODEL];
__device__ __nv_bfloat16 g_wo_lo[DMODEL * DMODEL];

// ---------------------------------------------------------------------------
// helpers
// ---------------------------------------------------------------------------
__device__ __forceinline__ uint32_t smem_u32(const void* p) {
  uint32_t a;
  asm("{ .reg .u64 t; cvta.to.shared.u64 t, %1; cvt.u32.u64 %0, t; }"
      : "=r"(a) : "l"(p));
  return a;
}
__device__ __forceinline__ void cpa16(uint32_t s, const void* g) {
  asm volatile("cp.async.cg.shared.global [%0], [%1], 16;"
               :: "r"(s), "l"(g) : "memory");
}
__device__ __forceinline__ void cpa_commit() {
  asm volatile("cp.async.commit_group;" ::: "memory");
}
__device__ __forceinline__ void cpa_wait0() {
  asm volatile("cp.async.wait_group 0;" ::: "memory");
}
__device__ __forceinline__ void ldsm_x4(uint32_t addr, uint32_t* r) {
  asm volatile("ldmatrix.sync.aligned.m8n8.x4.shared.b16 {%0,%1,%2,%3}, [%4];"
               : "=r"(r[0]), "=r"(r[1]), "=r"(r[2]), "=r"(r[3]) : "r"(addr));
}
__device__ __forceinline__ void ldsm_x4_t(uint32_t addr, uint32_t* r) {
  asm volatile("ldmatrix.sync.aligned.m8n8.x4.trans.shared.b16 {%0,%1,%2,%3}, [%4];"
               : "=r"(r[0]), "=r"(r[1]), "=r"(r[2]), "=r"(r[3]) : "r"(addr));
}
__device__ __forceinline__ void mma_bf16(float* d, const uint32_t* a,
                                         const uint32_t* b) {
  asm volatile(
      "mma.sync.aligned.m16n8k16.row.col.f32.bf16.bf16.f32 "
      "{%0,%1,%2,%3}, {%4,%5,%6,%7}, {%8,%9}, {%0,%1,%2,%3};"
      : "+f"(d[0]), "+f"(d[1]), "+f"(d[2]), "+f"(d[3])
      : "r"(a[0]), "r"(a[1]), "r"(a[2]), "r"(a[3]), "r"(b[0]), "r"(b[1]));
}
// pack: lo 16 bits = bf16(a), hi = bf16(b)
__device__ __forceinline__ uint32_t pack_bf16(float a, float b) {
  uint32_t r;
  asm("cvt.rn.bf16x2.f32 %0, %1, %2;" : "=r"(r) : "f"(b), "f"(a));
  return r;
}
__device__ __forceinline__ float bf16_round(float f) {
  return __bfloat162float(__float2bfloat16(f));
}

// ---------------------------------------------------------------------------
// Split-precision conversion kernels
// ---------------------------------------------------------------------------
__global__ void split_kernel(const float* __restrict__ src,
                             __nv_bfloat16* __restrict__ hi,
                             __nv_bfloat16* __restrict__ lo, int n) {
  int i = blockIdx.x * blockDim.x + threadIdx.x;
  if (i >= n) return;
  float f = src[i];
  __nv_bfloat16 h = __float2bfloat16(f);
  hi[i] = h;
  lo[i] = __float2bfloat16(f - __bfloat162float(h));
}

// w[K,N] fp32 -> th/tl [N,K] bf16 (transpose + split)
__global__ void transpose_split_kernel(const float* __restrict__ w,
                                       __nv_bfloat16* __restrict__ th,
                                       __nv_bfloat16* __restrict__ tl,
                                       int K, int N) {
  __shared__ float tile[32][33];
  int nx = blockIdx.x * 32 + threadIdx.x;
  int k0 = blockIdx.y * 32;
  for (int i = threadIdx.y; i < 32; i += 8)
    tile[i][threadIdx.x] = w[(size_t)(k0 + i) * N + nx];
  __syncthreads();
  for (int j = threadIdx.y; j < 32; j += 8) {
    int n = blockIdx.x * 32 + j;
    int kk = k0 + threadIdx.x;
    float f = tile[threadIdx.x][j];
    __nv_bfloat16 h = __float2bfloat16(f);
    th[(size_t)n * K + kk] = h;
    tl[(size_t)n * K + kk] = __float2bfloat16(f - __bfloat162float(h));
  }
}

// ---------------------------------------------------------------------------
// mma.sync bf16 split-precision GEMM with 2-stage cp.async pipeline.
// C[M,N] = A[M,K] @ Bt[N,K]^T. 128x128 CTA tile, BK=32, 256 thr, 8 warps.
// ---------------------------------------------------------------------------
#define SB 40                          // smem row stride (elements); conflict-free
#define T2E (128 * SB)                 // elements per tile (128 rows x BK=32 cols)
#define STG_E (4 * T2E)                // 4 tiles per stage
#define GEMM_SMEM (2 * STG_E * 2)      // 2 stages of bf16 = 81920 B

__global__ __launch_bounds__(256, 2) void gemm_mma_kernel(
    const __nv_bfloat16* __restrict__ Ahi, const __nv_bfloat16* __restrict__ Alo,
    const __nv_bfloat16* __restrict__ Bhi, const __nv_bfloat16* __restrict__ Blo,
    float* __restrict__ C, int M, int N, int K) {
  extern __shared__ __nv_bfloat16 smb[];
  const int tid = threadIdx.x;
  const int lane = tid & 31;
  const int wid = tid >> 5;
  const int wm = wid & 3;
  const int wn = wid >> 2;
  const int m0 = blockIdx.y * 128;
  const int n0 = blockIdx.x * 128;
  const uint32_t sbase = smem_u32(smb);

  const uint32_t OA_HI = 0, OA_LO = T2E, OB_HI = 2 * T2E, OB_LO = 3 * T2E;

  float acc[2][8][4];
#pragma unroll
  for (int i = 0; i < 2; ++i)
#pragma unroll
    for (int j = 0; j < 8; ++j)
#pragma unroll
      for (int q = 0; q < 4; ++q) acc[i][j][q] = 0.f;

  const int a_row = lane & 15;
  const int a_col = (lane >> 4) * 8;
  const int b_row = (lane & 7) + ((lane & 16) >> 1);
  const int b_col = lane & 8;

  // load map: tile has 512 16B-vectors (4 per row); 2 per thread
  const int l_r = tid >> 2;            // +64 per it
  const int l_c = (tid & 3) * 8;

  const int nchunks = K >> 5;          // K/32

  // prologue: load chunk 0 into stage 0
  {
    const int k0g = 0;
#pragma unroll
    for (int it = 0; it < 2; ++it) {
      int r = l_r + it * 64;
      const size_t ga = (size_t)(m0 + r) * K + k0g + l_c;
      const size_t gb = (size_t)(n0 + r) * K + k0g + l_c;
      uint32_t so = (uint32_t)(r * SB + l_c) * 2;
      cpa16(sbase + OA_HI * 2 + so, Ahi + ga);
      cpa16(sbase + OA_LO * 2 + so, Alo + ga);
      cpa16(sbase + OB_HI * 2 + so, Bhi + gb);
      cpa16(sbase + OB_LO * 2 + so, Blo + gb);
    }
    cpa_commit();
  }

  for (int c = 0; c < nchunks; ++c) {
    cpa_wait0();                        // chunk c resident
    __syncthreads();                    // stage (c+1)&1 free (compute c-1 done)
    if (c + 1 < nchunks) {              // prefetch chunk c+1
      const int k0g = (c + 1) << 5;
      const uint32_t stb = sbase + ((c + 1) & 1) * (STG_E * 2);
#pragma unroll
      for (int it = 0; it < 2; ++it) {
        int r = l_r + it * 64;
        const size_t ga = (size_t)(m0 + r) * K + k0g + l_c;
        const size_t gb = (size_t)(n0 + r) * K + k0g + l_c;
        uint32_t so = (uint32_t)(r * SB + l_c) * 2;
        cpa16(stb + OA_HI * 2 + so, Ahi + ga);
        cpa16(stb + OA_LO * 2 + so, Alo + ga);
        cpa16(stb + OB_HI * 2 + so, Bhi + gb);
        cpa16(stb + OB_LO * 2 + so, Blo + gb);
      }
      cpa_commit();
    }

    const uint32_t stg = sbase + (c & 1) * (STG_E * 2);
#pragma unroll
    for (int s = 0; s < 2; ++s) {       // 2 k-steps of 16
      const int k0 = s * 16;
      uint32_t ahi[2][4], alo[2][4];
#pragma unroll
      for (int mt = 0; mt < 2; ++mt) {
        uint32_t off = (uint32_t)((wm * 32 + mt * 16 + a_row) * SB + k0 + a_col) * 2;
        ldsm_x4(stg + OA_HI * 2 + off, ahi[mt]);
        ldsm_x4(stg + OA_LO * 2 + off, alo[mt]);
      }
#pragma unroll
      for (int nt2 = 0; nt2 < 4; ++nt2) {
        uint32_t bh[4], bl[4];
        uint32_t off = (uint32_t)((wn * 64 + nt2 * 16 + b_row) * SB + k0 + b_col) * 2;
        ldsm_x4(stg + OB_HI * 2 + off, bh);
        ldsm_x4(stg + OB_LO * 2 + off, bl);
#pragma unroll
        for (int mt = 0; mt < 2; ++mt) {
          mma_bf16(acc[mt][nt2 * 2], ahi[mt], bh);
          mma_bf16(acc[mt][nt2 * 2], ahi[mt], bl);
          mma_bf16(acc[mt][nt2 * 2], alo[mt], bh);
          mma_bf16(acc[mt][nt2 * 2 + 1], ahi[mt], bh + 2);
          mma_bf16(acc[mt][nt2 * 2 + 1], ahi[mt], bl + 2);
          mma_bf16(acc[mt][nt2 * 2 + 1], alo[mt], bh + 2);
        }
      }
    }
  }

#pragma unroll
  for (int mt = 0; mt < 2; ++mt) {
    int r0 = m0 + wm * 32 + mt * 16 + (lane >> 2);
#pragma unroll
    for (int nt = 0; nt < 8; ++nt) {
      int col = n0 + wn * 64 + nt * 8 + (lane & 3) * 2;
      float2 v0 = {acc[mt][nt][0], acc[mt][nt][1]};
      float2 v1 = {acc[mt][nt][2], acc[mt][nt][3]};
      *(float2*)(C + (size_t)r0 * N + col) = v0;
      *(float2*)(C + (size_t)(r0 + 8) * N + col) = v1;
    }
  }
}

// ---------------------------------------------------------------------------
// RoPE
// ---------------------------------------------------------------------------
__global__ void rope_kernel(float* __restrict__ t, const float* __restrict__ fcos,
                            const float* __restrict__ fsin, int nheads) {
  int idx = blockIdx.x * blockDim.x + threadIdx.x;
  int total = BATCH * SEQ * nheads * (HD / 2);
  if (idx >= total) return;
  int p = idx & 63;
  int rest = idx >> 6;
  int h = rest % nheads;
  rest /= nheads;
  int s = rest & (SEQ - 1);
  int b = rest >> 11;
  float c = fcos[s * 64 + p];
  float sn = fsin[s * 64 + p];
  float* base = t + ((size_t)(b * SEQ + s) * nheads + h) * HD + p * 2;
  float x0 = base[0], x1 = base[1];
  base[0] = x0 * c - x1 * sn;
  base[1] = x0 * sn + x1 * c;
}

// ---------------------------------------------------------------------------
// Tensor-core flash attention, split-precision bf16, causal.
// BLOCK_M=64 (4 warps x m16), BLOCK_N=64, D=128.
// Writes attention output directly as split bf16 (hi/lo) for the out-proj.
// ---------------------------------------------------------------------------
#define FSD 136                       // smem stride (elements)
#define FTE (64 * FSD)                // elements per tile
#define FA_SMEM (6 * FTE * 2)         // Qhi,Qlo,Khi,Klo,Vhi,Vlo = 104448 B

__global__ __launch_bounds__(128) void fa_mma_kernel(
    const float* __restrict__ q, const float* __restrict__ k,
    const float* __restrict__ v, __nv_bfloat16* __restrict__ ohi,
    __nv_bfloat16* __restrict__ olo) {
  extern __shared__ __nv_bfloat16 fsm[];
  const uint32_t sbase = smem_u32(fsm);
  const int tid = threadIdx.x;
  const int lane = tid & 31;
  const int w = tid >> 5;

  const int mt = gridDim.x - 1 - blockIdx.x;   // heavy tiles first
  const int m0 = mt * 64;
  const int h = blockIdx.y;
  const int b = blockIdx.z;
  const int g = h >> 2;
  const float scale = 0.08838834764831845f;    // 1/sqrt(128)

  const uint32_t QH = 0, QL = FTE, KH = 2 * FTE, KL = 3 * FTE, VH = 4 * FTE,
                 VL = 5 * FTE;

  // --- load Q tile (scaled, split) ---
#pragma unroll
  for (int it = 0; it < 16; ++it) {
    int i = tid + it * 128;
    int r = i >> 5;
    int cc = (i & 31) * 4;
    float4 f = *(const float4*)(q + ((size_t)(b * SEQ + m0 + r) * NH + h) * HD + cc);
    f.x *= scale; f.y *= scale; f.z *= scale; f.w *= scale;
    uint32_t e = r * FSD + cc;
    uint2 hv = {pack_bf16(f.x, f.y), pack_bf16(f.z, f.w)};
    uint2 lv = {pack_bf16(f.x - bf16_round(f.x), f.y - bf16_round(f.y)),
                pack_bf16(f.z - bf16_round(f.z), f.w - bf16_round(f.w))};
    *(uint2*)((char*)fsm + (size_t)(QH + e) * 2) = hv;
    *(uint2*)((char*)fsm + (size_t)(QL + e) * 2) = lv;
  }

  float m_lo = -1e30f, m_hi = -1e30f, l_lo = 0.f, l_hi = 0.f;
  float oacc[16][4];
#pragma unroll
  for (int i = 0; i < 16; ++i)
#pragma unroll
    for (int j = 0; j < 4; ++j) oacc[i][j] = 0.f;

  const int a_row = lane & 15;
  const int a_col = (lane >> 4) * 8;
  const int b_row = (lane & 7) + ((lane & 16) >> 1);
  const int b_col = lane & 8;

  for (int t = 0; t <= mt; ++t) {
    const int n0 = t * 64;
    __syncthreads();
#pragma unroll
    for (int it = 0; it < 16; ++it) {
      int i = tid + it * 128;
      int r = i >> 5;
      int cc = (i & 31) * 4;
      uint32_t e = r * FSD + cc;
      const size_t gi = ((size_t)(b * SEQ + n0 + r) * NKV + g) * HD + cc;
      float4 fk = *(const float4*)(k + gi);
      *(uint2*)((char*)fsm + (size_t)(KH + e) * 2) =
          make_uint2(pack_bf16(fk.x, fk.y), pack_bf16(fk.z, fk.w));
      *(uint2*)((char*)fsm + (size_t)(KL + e) * 2) =
          make_uint2(pack_bf16(fk.x - bf16_round(fk.x), fk.y - bf16_round(fk.y)),
                     pack_bf16(fk.z - bf16_round(fk.z), fk.w - bf16_round(fk.w)));
      float4 fv = *(const float4*)(v + gi);
      *(uint2*)((char*)fsm + (size_t)(VH + e) * 2) =
          make_uint2(pack_bf16(fv.x, fv.y), pack_bf16(fv.z, fv.w));
      *(uint2*)((char*)fsm + (size_t)(VL + e) * 2) =
          make_uint2(pack_bf16(fv.x - bf16_round(fv.x), fv.y - bf16_round(fv.y)),
                     pack_bf16(fv.z - bf16_round(fv.z), fv.w - bf16_round(fv.w)));
    }
    __syncthreads();

    // --- S = Q @ K^T ---
    float sacc[8][4];
#pragma unroll
    for (int i = 0; i < 8; ++i)
#pragma unroll
      for (int j = 0; j < 4; ++j) sacc[i][j] = 0.f;

#pragma unroll
    for (int kc = 0; kc < 8; ++kc) {
      uint32_t aq_off = (uint32_t)((w * 16 + a_row) * FSD + kc * 16 + a_col) * 2;
      uint32_t aqh[4], aql[4];
      ldsm_x4(sbase + QH * 2 + aq_off, aqh);
      ldsm_x4(sbase + QL * 2 + aq_off, aql);
#pragma unroll
      for (int np = 0; np < 4; ++np) {
        uint32_t bo = (uint32_t)((np * 16 + b_row) * FSD + kc * 16 + b_col) * 2;
        uint32_t bh[4], bl[4];
        ldsm_x4(sbase + KH * 2 + bo, bh);
        ldsm_x4(sbase + KL * 2 + bo, bl);
        mma_bf16(sacc[np * 2], aqh, bh);
        mma_bf16(sacc[np * 2], aqh, bl);
        mma_bf16(sacc[np * 2], aql, bh);
        mma_bf16(sacc[np * 2 + 1], aqh, bh + 2);
        mma_bf16(sacc[np * 2 + 1], aqh, bl + 2);
        mma_bf16(sacc[np * 2 + 1], aql, bh + 2);
      }
    }

    if (t == mt) {
      int row_lo = w * 16 + (lane >> 2);
      int row_hi = row_lo + 8;
#pragma unroll
      for (int nt = 0; nt < 8; ++nt) {
        int c0 = nt * 8 + (lane & 3) * 2;
        if (c0 > row_lo) sacc[nt][0] = -1e30f;
        if (c0 + 1 > row_lo) sacc[nt][1] = -1e30f;
        if (c0 > row_hi) sacc[nt][2] = -1e30f;
        if (c0 + 1 > row_hi) sacc[nt][3] = -1e30f;
      }
    }

    // --- online softmax ---
    float rmax_lo = -1e30f, rmax_hi = -1e30f;
#pragma unroll
    for (int nt = 0; nt < 8; ++nt) {
      rmax_lo = fmaxf(rmax_lo, fmaxf(sacc[nt][0], sacc[nt][1]));
      rmax_hi = fmaxf(rmax_hi, fmaxf(sacc[nt][2], sacc[nt][3]));
    }
#pragma unroll
    for (int d = 1; d < 4; d <<= 1) {
      rmax_lo = fmaxf(rmax_lo, __shfl_xor_sync(0xffffffffu, rmax_lo, d));
      rmax_hi = fmaxf(rmax_hi, __shfl_xor_sync(0xffffffffu, rmax_hi, d));
    }
    float mn_lo = fmaxf(m_lo, rmax_lo);
    float mn_hi = fmaxf(m_hi, rmax_hi);
    float f_lo = __expf(m_lo - mn_lo);
    float f_hi = __expf(m_hi - mn_hi);
    m_lo = mn_lo; m_hi = mn_hi;

    float rsum_lo = 0.f, rsum_hi = 0.f;
#pragma unroll
    for (int nt = 0; nt < 8; ++nt) {
      sacc[nt][0] = __expf(sacc[nt][0] - mn_lo);
      sacc[nt][1] = __expf(sacc[nt][1] - mn_lo);
      sacc[nt][2] = __expf(sacc[nt][2] - mn_hi);
      sacc[nt][3] = __expf(sacc[nt][3] - mn_hi);
      rsum_lo += sacc[nt][0] + sacc[nt][1];
      rsum_hi += sacc[nt][2] + sacc[nt][3];
    }
#pragma unroll
    for (int d = 1; d < 4; d <<= 1) {
      rsum_lo += __shfl_xor_sync(0xffffffffu, rsum_lo, d);
      rsum_hi += __shfl_xor_sync(0xffffffffu, rsum_hi, d);
    }
    l_lo = l_lo * f_lo + rsum_lo;
    l_hi = l_hi * f_hi + rsum_hi;
#pragma unroll
    for (int i = 0; i < 16; ++i) {
      oacc[i][0] *= f_lo; oacc[i][1] *= f_lo;
      oacc[i][2] *= f_hi; oacc[i][3] *= f_hi;
    }

    // --- O += P @ V ---
#pragma unroll
    for (int kt = 0; kt < 4; ++kt) {
      const float* s0 = sacc[2 * kt];
      const float* s1 = sacc[2 * kt + 1];
      uint32_t ph[4], pl[4];
      ph[0] = pack_bf16(s0[0], s0[1]);
      ph[1] = pack_bf16(s0[2], s0[3]);
      ph[2] = pack_bf16(s1[0], s1[1]);
      ph[3] = pack_bf16(s1[2], s1[3]);
      pl[0] = pack_bf16(s0[0] - bf16_round(s0[0]), s0[1] - bf16_round(s0[1]));
      pl[1] = pack_bf16(s0[2] - bf16_round(s0[2]), s0[3] - bf16_round(s0[3]));
      pl[2] = pack_bf16(s1[0] - bf16_round(s1[0]), s1[1] - bf16_round(s1[1]));
      pl[3] = pack_bf16(s1[2] - bf16_round(s1[2]), s1[3] - bf16_round(s1[3]));
#pragma unroll
      for (int dp = 0; dp < 8; ++dp) {
        uint32_t vo = (uint32_t)((kt * 16 + (lane & 15)) * FSD + dp * 16 +
                                 ((lane >> 4) << 3)) * 2;
        uint32_t vh[4], vl[4];
        ldsm_x4_t(sbase + VH * 2 + vo, vh);
        ldsm_x4_t(sbase + VL * 2 + vo, vl);
        mma_bf16(oacc[dp * 2], ph, vh);
        mma_bf16(oacc[dp * 2], pl, vh);
        mma_bf16(oacc[dp * 2], ph, vl);
        mma_bf16(oacc[dp * 2 + 1], ph, vh + 2);
        mma_bf16(oacc[dp * 2 + 1], pl, vh + 2);
        mma_bf16(oacc[dp * 2 + 1], ph, vl + 2);
      }
    }
  }

  // --- epilogue: normalize, split to bf16 hi/lo, write [b,s,h,d] ---
  float inv_lo = 1.f / l_lo;
  float inv_hi = 1.f / l_hi;
  int r_lo = m0 + w * 16 + (lane >> 2);
  int r_hi = r_lo + 8;
#pragma unroll
  for (int dt = 0; dt < 16; ++dt) {
    int col = dt * 8 + (lane & 3) * 2;
    float a0 = oacc[dt][0] * inv_lo, a1 = oacc[dt][1] * inv_lo;
    float b0 = oacc[dt][2] * inv_hi, b1 = oacc[dt][3] * inv_hi;
    size_t i0 = ((size_t)(b * SEQ + r_lo) * NH + h) * HD + col;
    size_t i1 = ((size_t)(b * SEQ + r_hi) * NH + h) * HD + col;
    *(uint32_t*)(ohi + i0) = pack_bf16(a0, a1);
    *(uint32_t*)(olo + i0) = pack_bf16(a0 - bf16_round(a0), a1 - bf16_round(a1));
    *(uint32_t*)(ohi + i1) = pack_bf16(b0, b1);
    *(uint32_t*)(olo + i1) = pack_bf16(b0 - bf16_round(b0), b1 - bf16_round(b1));
  }
}

// ---------------------------------------------------------------------------
// Launch
// ---------------------------------------------------------------------------
extern "C" void kernel_launch(void* const* d_in, const int* in_sizes, int n_in,
                              void* d_out, int out_size) {
  const float* x    = (const float*)d_in[0];
  const float* fcos = (const float*)d_in[1];
  const float* fsin = (const float*)d_in[2];
  // d_in[3] = mask (causal mask applied analytically)
  const float* wq = (const float*)d_in[4];
  const float* wk = (const float*)d_in[5];
  const float* wv = (const float*)d_in[6];
  const float* wo = (const float*)d_in[7];
  float* out = (float*)d_out;

  float *q, *k, *v;
  cudaGetSymbolAddress((void**)&q, g_q);
  cudaGetSymbolAddress((void**)&k, g_k);
  cudaGetSymbolAddress((void**)&v, g_v);
  __nv_bfloat16 *xh, *xl, *aoh, *aol, *wqh, *wql, *wkh, *wkl, *wvh, *wvl, *woh, *wol;
  cudaGetSymbolAddress((void**)&xh, g_x_hi);
  cudaGetSymbolAddress((void**)&xl, g_x_lo);
  cudaGetSymbolAddress((void**)&aoh, g_ao_hi);
  cudaGetSymbolAddress((void**)&aol, g_ao_lo);
  cudaGetSymbolAddress((void**)&wqh, g_wq_hi);
  cudaGetSymbolAddress((void**)&wql, g_wq_lo);
  cudaGetSymbolAddress((void**)&wkh, g_wk_hi);
  cudaGetSymbolAddress((void**)&wkl, g_wk_lo);
  cudaGetSymbolAddress((void**)&wvh, g_wv_hi);
  cudaGetSymbolAddress((void**)&wvl, g_wv_lo);
  cudaGetSymbolAddress((void**)&woh, g_wo_hi);
  cudaGetSymbolAddress((void**)&wol, g_wo_lo);

  static bool attr_done = false;
  if (!attr_done) {
    cudaFuncSetAttribute(gemm_mma_kernel,
                         cudaFuncAttributeMaxDynamicSharedMemorySize, GEMM_SMEM);
    cudaFuncSetAttribute(fa_mma_kernel,
                         cudaFuncAttributeMaxDynamicSharedMemorySize, FA_SMEM);
    attr_done = true;
  }

  // split inputs / transpose+split weights
  {
    int nx = MTOK * DMODEL;
    split_kernel<<<(nx + 255) / 256, 256>>>(x, xh, xl, nx);
    dim3 blk(32, 8);
    transpose_split_kernel<<<dim3(DMODEL / 32, DMODEL / 32), blk>>>(wq, wqh, wql, DMODEL, DMODEL);
    transpose_split_kernel<<<dim3(KVDIM / 32, DMODEL / 32), blk>>>(wk, wkh, wkl, DMODEL, KVDIM);
    transpose_split_kernel<<<dim3(KVDIM / 32, DMODEL / 32), blk>>>(wv, wvh, wvl, DMODEL, KVDIM);
    transpose_split_kernel<<<dim3(DMODEL / 32, DMODEL / 32), blk>>>(wo, woh, wol, DMODEL, DMODEL);
  }

  // projections on tensor cores (pipelined)
  gemm_mma_kernel<<<dim3(DMODEL / 128, MTOK / 128), 256, GEMM_SMEM>>>(
      xh, xl, wqh, wql, q, MTOK, DMODEL, DMODEL);
  gemm_mma_kernel<<<dim3(KVDIM / 128, MTOK / 128), 256, GEMM_SMEM>>>(
      xh, xl, wkh, wkl, k, MTOK, KVDIM, DMODEL);
  gemm_mma_kernel<<<dim3(KVDIM / 128, MTOK / 128), 256, GEMM_SMEM>>>(
      xh, xl, wvh, wvl, v, MTOK, KVDIM, DMODEL);

  // RoPE
  {
    int tq = BATCH * SEQ * NH * (HD / 2);
    rope_kernel<<<(tq + 255) / 256, 256>>>(q, fcos, fsin, NH);
    int tk = BATCH * SEQ * NKV * (HD / 2);
    rope_kernel<<<(tk + 255) / 256, 256>>>(k, fcos, fsin, NKV);
  }

  // Tensor-core flash attention -> split bf16 output
  fa_mma_kernel<<<dim3(SEQ / 64, NH, BATCH), 128, FA_SMEM>>>(q, k, v, aoh, aol);

  // Output projection on tensor cores
  gemm_mma_kernel<<<dim3(DMODEL / 128, MTOK / 128), 256, GEMM_SMEM>>>(
      aoh, aol, woh, wol, out, MTOK, DMODEL, DMODEL);
}

// round 8
// speedup vs baseline: 3.4200x; 1.0239x over previous
#include <cuda_runtime.h>
#include <cuda_bf16.h>
#include <cstdint>
#include <math.h>

// Problem dims (fixed by reference)
#define BATCH 2
#define SEQ 2048
#define DMODEL 2048
#define NH 16
#define NKV 4
#define HD 128
#define MTOK (BATCH * SEQ)          // 4096 tokens
#define KVDIM (NKV * HD)            // 512

// ---------------------------------------------------------------------------
// Scratch (device globals; runtime allocation is forbidden)
// ---------------------------------------------------------------------------
__device__ float g_q[MTOK * NH * HD];
__device__ float g_k[MTOK * KVDIM];

// split-precision bf16 operands
__device__ __nv_bfloat16 g_x_hi[MTOK * DMODEL];
__device__ __nv_bfloat16 g_x_lo[MTOK * DMODEL];
__device__ __nv_bfloat16 g_ao_hi[MTOK * DMODEL];
__device__ __nv_bfloat16 g_ao_lo[MTOK * DMODEL];
__device__ __nv_bfloat16 g_qh[MTOK * NH * HD];
__device__ __nv_bfloat16 g_ql[MTOK * NH * HD];
__device__ __nv_bfloat16 g_kh[MTOK * KVDIM];
__device__ __nv_bfloat16 g_kl[MTOK * KVDIM];
__device__ __nv_bfloat16 g_vh[MTOK * KVDIM];
__device__ __nv_bfloat16 g_vl[MTOK * KVDIM];
// weights transposed to [N, K]
__device__ __nv_bfloat16 g_wq_hi[DMODEL * DMODEL];
__device__ __nv_bfloat16 g_wq_lo[DMODEL * DMODEL];
__device__ __nv_bfloat16 g_wk_hi[KVDIM * DMODEL];
__device__ __nv_bfloat16 g_wk_lo[KVDIM * DMODEL];
__device__ __nv_bfloat16 g_wv_hi[KVDIM * DMODEL];
__device__ __nv_bfloat16 g_wv_lo[KVDIM * DMODEL];
__device__ __nv_bfloat16 g_wo_hi[DMODEL * DMODEL];
__device__ __nv_bfloat16 g_wo_lo[DMODEL * DMODEL];

// ---------------------------------------------------------------------------
// helpers
// ---------------------------------------------------------------------------
__device__ __forceinline__ uint32_t smem_u32(const void* p) {
  uint32_t a;
  asm("{ .reg .u64 t; cvta.to.shared.u64 t, %1; cvt.u32.u64 %0, t; }"
      : "=r"(a) : "l"(p));
  return a;
}
__device__ __forceinline__ void cpa16(uint32_t s, const void* g) {
  asm volatile("cp.async.cg.shared.global [%0], [%1], 16;"
               :: "r"(s), "l"(g) : "memory");
}
__device__ __forceinline__ void cpa_commit() {
  asm volatile("cp.async.commit_group;" ::: "memory");
}
__device__ __forceinline__ void cpa_wait0() {
  asm volatile("cp.async.wait_group 0;" ::: "memory");
}
__device__ __forceinline__ void ldsm_x4(uint32_t addr, uint32_t* r) {
  asm volatile("ldmatrix.sync.aligned.m8n8.x4.shared.b16 {%0,%1,%2,%3}, [%4];"
               : "=r"(r[0]), "=r"(r[1]), "=r"(r[2]), "=r"(r[3]) : "r"(addr));
}
__device__ __forceinline__ void ldsm_x4_t(uint32_t addr, uint32_t* r) {
  asm volatile("ldmatrix.sync.aligned.m8n8.x4.trans.shared.b16 {%0,%1,%2,%3}, [%4];"
               : "=r"(r[0]), "=r"(r[1]), "=r"(r[2]), "=r"(r[3]) : "r"(addr));
}
__device__ __forceinline__ void mma_bf16(float* d, const uint32_t* a,
                                         const uint32_t* b) {
  asm volatile(
      "mma.sync.aligned.m16n8k16.row.col.f32.bf16.bf16.f32 "
      "{%0,%1,%2,%3}, {%4,%5,%6,%7}, {%8,%9}, {%0,%1,%2,%3};"
      : "+f"(d[0]), "+f"(d[1]), "+f"(d[2]), "+f"(d[3])
      : "r"(a[0]), "r"(a[1]), "r"(a[2]), "r"(a[3]), "r"(b[0]), "r"(b[1]));
}
// pack: lo 16 bits = bf16(a), hi = bf16(b)
__device__ __forceinline__ uint32_t pack_bf16(float a, float b) {
  uint32_t r;
  asm("cvt.rn.bf16x2.f32 %0, %1, %2;" : "=r"(r) : "f"(b), "f"(a));
  return r;
}
__device__ __forceinline__ float bf16_round(float f) {
  return __bfloat162float(__float2bfloat16(f));
}

// ---------------------------------------------------------------------------
// Split-precision conversion kernels
// ---------------------------------------------------------------------------
__global__ void split_kernel(const float* __restrict__ src,
                             __nv_bfloat16* __restrict__ hi,
                             __nv_bfloat16* __restrict__ lo, int n) {
  int i = blockIdx.x * blockDim.x + threadIdx.x;
  if (i >= n) return;
  float f = src[i];
  __nv_bfloat16 h = __float2bfloat16(f);
  hi[i] = h;
  lo[i] = __float2bfloat16(f - __bfloat162float(h));
}

// w[K,N] fp32 -> th/tl [N,K] bf16 (transpose + split)
__global__ void transpose_split_kernel(const float* __restrict__ w,
                                       __nv_bfloat16* __restrict__ th,
                                       __nv_bfloat16* __restrict__ tl,
                                       int K, int N) {
  __shared__ float tile[32][33];
  int nx = blockIdx.x * 32 + threadIdx.x;
  int k0 = blockIdx.y * 32;
  for (int i = threadIdx.y; i < 32; i += 8)
    tile[i][threadIdx.x] = w[(size_t)(k0 + i) * N + nx];
  __syncthreads();
  for (int j = threadIdx.y; j < 32; j += 8) {
    int n = blockIdx.x * 32 + j;
    int kk = k0 + threadIdx.x;
    float f = tile[threadIdx.x][j];
    __nv_bfloat16 h = __float2bfloat16(f);
    th[(size_t)n * K + kk] = h;
    tl[(size_t)n * K + kk] = __float2bfloat16(f - __bfloat162float(h));
  }
}

// RoPE + optional scale + split to bf16 hi/lo (packed 32-bit pair writes)
__global__ void rope_split_kernel(const float* __restrict__ t,
                                  const float* __restrict__ fcos,
                                  const float* __restrict__ fsin,
                                  __nv_bfloat16* __restrict__ th,
                                  __nv_bfloat16* __restrict__ tl,
                                  int nheads, float scale) {
  int idx = blockIdx.x * blockDim.x + threadIdx.x;
  int total = BATCH * SEQ * nheads * (HD / 2);
  if (idx >= total) return;
  int p = idx & 63;
  int rest = idx >> 6;
  int h = rest % nheads;
  rest /= nheads;
  int s = rest & (SEQ - 1);
  int b = rest >> 11;
  float c = fcos[s * 64 + p];
  float sn = fsin[s * 64 + p];
  size_t off = ((size_t)(b * SEQ + s) * nheads + h) * HD + p * 2;
  const float* base = t + off;
  float x0 = base[0], x1 = base[1];
  float o0 = (x0 * c - x1 * sn) * scale;
  float o1 = (x0 * sn + x1 * c) * scale;
  *(uint32_t*)(th + off) = pack_bf16(o0, o1);
  *(uint32_t*)(tl + off) =
      pack_bf16(o0 - bf16_round(o0), o1 - bf16_round(o1));
}

// ---------------------------------------------------------------------------
// mma.sync bf16 split-precision GEMM with 2-stage cp.async pipeline.
// C[M,N] = A[M,K] @ Bt[N,K]^T. 128x128 CTA tile, BK=32, 256 thr, 8 warps.
// SPLIT_OUT: write bf16 hi/lo instead of fp32.
// ---------------------------------------------------------------------------
#define SB 40
#define T2E (128 * SB)
#define STG_E (4 * T2E)
#define GEMM_SMEM (2 * STG_E * 2)      // 81920 B

template <bool SPLIT_OUT>
__global__ __launch_bounds__(256, 2) void gemm_mma_kernel(
    const __nv_bfloat16* __restrict__ Ahi, const __nv_bfloat16* __restrict__ Alo,
    const __nv_bfloat16* __restrict__ Bhi, const __nv_bfloat16* __restrict__ Blo,
    float* __restrict__ C, __nv_bfloat16* __restrict__ Chi,
    __nv_bfloat16* __restrict__ Clo, int M, int N, int K) {
  extern __shared__ __nv_bfloat16 smb[];
  const int tid = threadIdx.x;
  const int lane = tid & 31;
  const int wid = tid >> 5;
  const int wm = wid & 3;
  const int wn = wid >> 2;
  const int m0 = blockIdx.y * 128;
  const int n0 = blockIdx.x * 128;
  const uint32_t sbase = smem_u32(smb);

  const uint32_t OA_HI = 0, OA_LO = T2E, OB_HI = 2 * T2E, OB_LO = 3 * T2E;

  float acc[2][8][4];
#pragma unroll
  for (int i = 0; i < 2; ++i)
#pragma unroll
    for (int j = 0; j < 8; ++j)
#pragma unroll
      for (int q = 0; q < 4; ++q) acc[i][j][q] = 0.f;

  const int a_row = lane & 15;
  const int a_col = (lane >> 4) * 8;
  const int b_row = (lane & 7) + ((lane & 16) >> 1);
  const int b_col = lane & 8;

  const int l_r = tid >> 2;
  const int l_c = (tid & 3) * 8;

  const int nchunks = K >> 5;

  {
#pragma unroll
    for (int it = 0; it < 2; ++it) {
      int r = l_r + it * 64;
      const size_t ga = (size_t)(m0 + r) * K + l_c;
      const size_t gb = (size_t)(n0 + r) * K + l_c;
      uint32_t so = (uint32_t)(r * SB + l_c) * 2;
      cpa16(sbase + OA_HI * 2 + so, Ahi + ga);
      cpa16(sbase + OA_LO * 2 + so, Alo + ga);
      cpa16(sbase + OB_HI * 2 + so, Bhi + gb);
      cpa16(sbase + OB_LO * 2 + so, Blo + gb);
    }
    cpa_commit();
  }

  for (int c = 0; c < nchunks; ++c) {
    cpa_wait0();
    __syncthreads();
    if (c + 1 < nchunks) {
      const int k0g = (c + 1) << 5;
      const uint32_t stb = sbase + ((c + 1) & 1) * (STG_E * 2);
#pragma unroll
      for (int it = 0; it < 2; ++it) {
        int r = l_r + it * 64;
        const size_t ga = (size_t)(m0 + r) * K + k0g + l_c;
        const size_t gb = (size_t)(n0 + r) * K + k0g + l_c;
        uint32_t so = (uint32_t)(r * SB + l_c) * 2;
        cpa16(stb + OA_HI * 2 + so, Ahi + ga);
        cpa16(stb + OA_LO * 2 + so, Alo + ga);
        cpa16(stb + OB_HI * 2 + so, Bhi + gb);
        cpa16(stb + OB_LO * 2 + so, Blo + gb);
      }
      cpa_commit();
    }

    const uint32_t stg = sbase + (c & 1) * (STG_E * 2);
#pragma unroll
    for (int s = 0; s < 2; ++s) {
      const int k0 = s * 16;
      uint32_t ahi[2][4], alo[2][4];
#pragma unroll
      for (int mt = 0; mt < 2; ++mt) {
        uint32_t off = (uint32_t)((wm * 32 + mt * 16 + a_row) * SB + k0 + a_col) * 2;
        ldsm_x4(stg + OA_HI * 2 + off, ahi[mt]);
        ldsm_x4(stg + OA_LO * 2 + off, alo[mt]);
      }
#pragma unroll
      for (int nt2 = 0; nt2 < 4; ++nt2) {
        uint32_t bh[4], bl[4];
        uint32_t off = (uint32_t)((wn * 64 + nt2 * 16 + b_row) * SB + k0 + b_col) * 2;
        ldsm_x4(stg + OB_HI * 2 + off, bh);
        ldsm_x4(stg + OB_LO * 2 + off, bl);
#pragma unroll
        for (int mt = 0; mt < 2; ++mt) {
          mma_bf16(acc[mt][nt2 * 2], ahi[mt], bh);
          mma_bf16(acc[mt][nt2 * 2], ahi[mt], bl);
          mma_bf16(acc[mt][nt2 * 2], alo[mt], bh);
          mma_bf16(acc[mt][nt2 * 2 + 1], ahi[mt], bh + 2);
          mma_bf16(acc[mt][nt2 * 2 + 1], ahi[mt], bl + 2);
          mma_bf16(acc[mt][nt2 * 2 + 1], alo[mt], bh + 2);
        }
      }
    }
  }

#pragma unroll
  for (int mt = 0; mt < 2; ++mt) {
    int r0 = m0 + wm * 32 + mt * 16 + (lane >> 2);
#pragma unroll
    for (int nt = 0; nt < 8; ++nt) {
      int col = n0 + wn * 64 + nt * 8 + (lane & 3) * 2;
      if (SPLIT_OUT) {
        float a0 = acc[mt][nt][0], a1 = acc[mt][nt][1];
        float b0 = acc[mt][nt][2], b1 = acc[mt][nt][3];
        *(uint32_t*)(Chi + (size_t)r0 * N + col) = pack_bf16(a0, a1);
        *(uint32_t*)(Clo + (size_t)r0 * N + col) =
            pack_bf16(a0 - bf16_round(a0), a1 - bf16_round(a1));
        *(uint32_t*)(Chi + (size_t)(r0 + 8) * N + col) = pack_bf16(b0, b1);
        *(uint32_t*)(Clo + (size_t)(r0 + 8) * N + col) =
            pack_bf16(b0 - bf16_round(b0), b1 - bf16_round(b1));
      } else {
        float2 v0 = {acc[mt][nt][0], acc[mt][nt][1]};
        float2 v1 = {acc[mt][nt][2], acc[mt][nt][3]};
        *(float2*)(C + (size_t)r0 * N + col) = v0;
        *(float2*)(C + (size_t)(r0 + 8) * N + col) = v1;
      }
    }
  }
}

// ---------------------------------------------------------------------------
// Tensor-core flash attention on preconverted split-bf16 operands.
// BLOCK_M=64 (4 warps x m16), BLOCK_N=64, D=128.
// ---------------------------------------------------------------------------
#define FSD 136                       // smem stride (elements)
#define FTE (64 * FSD)                // elements per tile
#define FA_SMEM (6 * FTE * 2)         // 104448 B

__global__ __launch_bounds__(128) void fa_mma_kernel(
    const __nv_bfloat16* __restrict__ qh, const __nv_bfloat16* __restrict__ ql,
    const __nv_bfloat16* __restrict__ kh, const __nv_bfloat16* __restrict__ kl,
    const __nv_bfloat16* __restrict__ vh, const __nv_bfloat16* __restrict__ vl,
    __nv_bfloat16* __restrict__ ohi, __nv_bfloat16* __restrict__ olo) {
  extern __shared__ __nv_bfloat16 fsm[];
  const uint32_t sbase = smem_u32(fsm);
  const int tid = threadIdx.x;
  const int lane = tid & 31;
  const int w = tid >> 5;

  const int mt = gridDim.x - 1 - blockIdx.x;   // heavy tiles first
  const int m0 = mt * 64;
  const int h = blockIdx.y;
  const int b = blockIdx.z;
  const int g = h >> 2;

  const uint32_t QH = 0, QL = FTE, KH = 2 * FTE, KL = 3 * FTE, VH = 4 * FTE,
                 VL = 5 * FTE;

  // --- async-load Q tile (pre-scaled, pre-split) ---
  {
    const int r = tid >> 4;            // rows 0..63 over 8 iters? 128thr/16vec
    const int cvec = (tid & 15) * 8;   // element col
#pragma unroll
    for (int it = 0; it < 8; ++it) {
      int row = r + it * 8;
      size_t gi = ((size_t)(b * SEQ + m0 + row) * NH + h) * HD + cvec;
      uint32_t e = (uint32_t)(row * FSD + cvec) * 2;
      cpa16(sbase + QH * 2 + e, qh + gi);
      cpa16(sbase + QL * 2 + e, ql + gi);
    }
    cpa_commit();
  }

  float m_lo = -1e30f, m_hi = -1e30f, l_lo = 0.f, l_hi = 0.f;
  float oacc[16][4];
#pragma unroll
  for (int i = 0; i < 16; ++i)
#pragma unroll
    for (int j = 0; j < 4; ++j) oacc[i][j] = 0.f;

  const int a_row = lane & 15;
  const int a_col = (lane >> 4) * 8;
  const int b_row = (lane & 7) + ((lane & 16) >> 1);
  const int b_col = lane & 8;

  for (int t = 0; t <= mt; ++t) {
    const int n0 = t * 64;
    __syncthreads();                   // previous compute done
    {
      const int r = tid >> 4;
      const int cvec = (tid & 15) * 8;
#pragma unroll
      for (int it = 0; it < 8; ++it) {
        int row = r + it * 8;
        size_t gi = ((size_t)(b * SEQ + n0 + row) * NKV + g) * HD + cvec;
        uint32_t e = (uint32_t)(row * FSD + cvec) * 2;
        cpa16(sbase + KH * 2 + e, kh + gi);
        cpa16(sbase + KL * 2 + e, kl + gi);
        cpa16(sbase + VH * 2 + e, vh + gi);
        cpa16(sbase + VL * 2 + e, vl + gi);
      }
      cpa_commit();
    }
    cpa_wait0();
    __syncthreads();

    // --- S = Q @ K^T ---
    float sacc[8][4];
#pragma unroll
    for (int i = 0; i < 8; ++i)
#pragma unroll
      for (int j = 0; j < 4; ++j) sacc[i][j] = 0.f;

#pragma unroll
    for (int kc = 0; kc < 8; ++kc) {
      uint32_t aq_off = (uint32_t)((w * 16 + a_row) * FSD + kc * 16 + a_col) * 2;
      uint32_t aqh[4], aql[4];
      ldsm_x4(sbase + QH * 2 + aq_off, aqh);
      ldsm_x4(sbase + QL * 2 + aq_off, aql);
#pragma unroll
      for (int np = 0; np < 4; ++np) {
        uint32_t bo = (uint32_t)((np * 16 + b_row) * FSD + kc * 16 + b_col) * 2;
        uint32_t bh[4], bl[4];
        ldsm_x4(sbase + KH * 2 + bo, bh);
        ldsm_x4(sbase + KL * 2 + bo, bl);
        mma_bf16(sacc[np * 2], aqh, bh);
        mma_bf16(sacc[np * 2], aqh, bl);
        mma_bf16(sacc[np * 2], aql, bh);
        mma_bf16(sacc[np * 2 + 1], aqh, bh + 2);
        mma_bf16(sacc[np * 2 + 1], aqh, bl + 2);
        mma_bf16(sacc[np * 2 + 1], aql, bh + 2);
      }
    }

    if (t == mt) {
      int row_lo = w * 16 + (lane >> 2);
      int row_hi = row_lo + 8;
#pragma unroll
      for (int nt = 0; nt < 8; ++nt) {
        int c0 = nt * 8 + (lane & 3) * 2;
        if (c0 > row_lo) sacc[nt][0] = -1e30f;
        if (c0 + 1 > row_lo) sacc[nt][1] = -1e30f;
        if (c0 > row_hi) sacc[nt][2] = -1e30f;
        if (c0 + 1 > row_hi) sacc[nt][3] = -1e30f;
      }
    }

    // --- online softmax ---
    float rmax_lo = -1e30f, rmax_hi = -1e30f;
#pragma unroll
    for (int nt = 0; nt < 8; ++nt) {
      rmax_lo = fmaxf(rmax_lo, fmaxf(sacc[nt][0], sacc[nt][1]));
      rmax_hi = fmaxf(rmax_hi, fmaxf(sacc[nt][2], sacc[nt][3]));
    }
#pragma unroll
    for (int d = 1; d < 4; d <<= 1) {
      rmax_lo = fmaxf(rmax_lo, __shfl_xor_sync(0xffffffffu, rmax_lo, d));
      rmax_hi = fmaxf(rmax_hi, __shfl_xor_sync(0xffffffffu, rmax_hi, d));
    }
    float mn_lo = fmaxf(m_lo, rmax_lo);
    float mn_hi = fmaxf(m_hi, rmax_hi);
    float f_lo = __expf(m_lo - mn_lo);
    float f_hi = __expf(m_hi - mn_hi);
    m_lo = mn_lo; m_hi = mn_hi;

    float rsum_lo = 0.f, rsum_hi = 0.f;
#pragma unroll
    for (int nt = 0; nt < 8; ++nt) {
      sacc[nt][0] = __expf(sacc[nt][0] - mn_lo);
      sacc[nt][1] = __expf(sacc[nt][1] - mn_lo);
      sacc[nt][2] = __expf(sacc[nt][2] - mn_hi);
      sacc[nt][3] = __expf(sacc[nt][3] - mn_hi);
      rsum_lo += sacc[nt][0] + sacc[nt][1];
      rsum_hi += sacc[nt][2] + sacc[nt][3];
    }
#pragma unroll
    for (int d = 1; d < 4; d <<= 1) {
      rsum_lo += __shfl_xor_sync(0xffffffffu, rsum_lo, d);
      rsum_hi += __shfl_xor_sync(0xffffffffu, rsum_hi, d);
    }
    l_lo = l_lo * f_lo + rsum_lo;
    l_hi = l_hi * f_hi + rsum_hi;
#pragma unroll
    for (int i = 0; i < 16; ++i) {
      oacc[i][0] *= f_lo; oacc[i][1] *= f_lo;
      oacc[i][2] *= f_hi; oacc[i][3] *= f_hi;
    }

    // --- O += P @ V ---
#pragma unroll
    for (int kt = 0; kt < 4; ++kt) {
      const float* s0 = sacc[2 * kt];
      const float* s1 = sacc[2 * kt + 1];
      uint32_t ph[4], pl[4];
      ph[0] = pack_bf16(s0[0], s0[1]);
      ph[1] = pack_bf16(s0[2], s0[3]);
      ph[2] = pack_bf16(s1[0], s1[1]);
      ph[3] = pack_bf16(s1[2], s1[3]);
      pl[0] = pack_bf16(s0[0] - bf16_round(s0[0]), s0[1] - bf16_round(s0[1]));
      pl[1] = pack_bf16(s0[2] - bf16_round(s0[2]), s0[3] - bf16_round(s0[3]));
      pl[2] = pack_bf16(s1[0] - bf16_round(s1[0]), s1[1] - bf16_round(s1[1]));
      pl[3] = pack_bf16(s1[2] - bf16_round(s1[2]), s1[3] - bf16_round(s1[3]));
#pragma unroll
      for (int dp = 0; dp < 8; ++dp) {
        uint32_t vo = (uint32_t)((kt * 16 + (lane & 15)) * FSD + dp * 16 +
                                 ((lane >> 4) << 3)) * 2;
        uint32_t vhf[4], vlf[4];
        ldsm_x4_t(sbase + VH * 2 + vo, vhf);
        ldsm_x4_t(sbase + VL * 2 + vo, vlf);
        mma_bf16(oacc[dp * 2], ph, vhf);
        mma_bf16(oacc[dp * 2], pl, vhf);
        mma_bf16(oacc[dp * 2], ph, vlf);
        mma_bf16(oacc[dp * 2 + 1], ph, vhf + 2);
        mma_bf16(oacc[dp * 2 + 1], pl, vhf + 2);
        mma_bf16(oacc[dp * 2 + 1], ph, vlf + 2);
      }
    }
  }

  // --- epilogue: normalize, split to bf16 hi/lo, write [b,s,h,d] ---
  float inv_lo = 1.f / l_lo;
  float inv_hi = 1.f / l_hi;
  int r_lo = m0 + w * 16 + (lane >> 2);
  int r_hi = r_lo + 8;
#pragma unroll
  for (int dt = 0; dt < 16; ++dt) {
    int col = dt * 8 + (lane & 3) * 2;
    float a0 = oacc[dt][0] * inv_lo, a1 = oacc[dt][1] * inv_lo;
    float b0 = oacc[dt][2] * inv_hi, b1 = oacc[dt][3] * inv_hi;
    size_t i0 = ((size_t)(b * SEQ + r_lo) * NH + h) * HD + col;
    size_t i1 = ((size_t)(b * SEQ + r_hi) * NH + h) * HD + col;
    *(uint32_t*)(ohi + i0) = pack_bf16(a0, a1);
    *(uint32_t*)(olo + i0) = pack_bf16(a0 - bf16_round(a0), a1 - bf16_round(a1));
    *(uint32_t*)(ohi + i1) = pack_bf16(b0, b1);
    *(uint32_t*)(olo + i1) = pack_bf16(b0 - bf16_round(b0), b1 - bf16_round(b1));
  }
}

// ---------------------------------------------------------------------------
// Launch
// ---------------------------------------------------------------------------
extern "C" void kernel_launch(void* const* d_in, const int* in_sizes, int n_in,
                              void* d_out, int out_size) {
  const float* x    = (const float*)d_in[0];
  const float* fcos = (const float*)d_in[1];
  const float* fsin = (const float*)d_in[2];
  // d_in[3] = mask (causal mask applied analytically)
  const float* wq = (const float*)d_in[4];
  const float* wk = (const float*)d_in[5];
  const float* wv = (const float*)d_in[6];
  const float* wo = (const float*)d_in[7];
  float* out = (float*)d_out;

  float *q, *k;
  cudaGetSymbolAddress((void**)&q, g_q);
  cudaGetSymbolAddress((void**)&k, g_k);
  __nv_bfloat16 *xh, *xl, *aoh, *aol, *qh, *ql, *kh, *kl, *vh, *vl;
  __nv_bfloat16 *wqh, *wql, *wkh, *wkl, *wvh, *wvl, *woh, *wol;
  cudaGetSymbolAddress((void**)&xh, g_x_hi);
  cudaGetSymbolAddress((void**)&xl, g_x_lo);
  cudaGetSymbolAddress((void**)&aoh, g_ao_hi);
  cudaGetSymbolAddress((void**)&aol, g_ao_lo);
  cudaGetSymbolAddress((void**)&qh, g_qh);
  cudaGetSymbolAddress((void**)&ql, g_ql);
  cudaGetSymbolAddress((void**)&kh, g_kh);
  cudaGetSymbolAddress((void**)&kl, g_kl);
  cudaGetSymbolAddress((void**)&vh, g_vh);
  cudaGetSymbolAddress((void**)&vl, g_vl);
  cudaGetSymbolAddress((void**)&wqh, g_wq_hi);
  cudaGetSymbolAddress((void**)&wql, g_wq_lo);
  cudaGetSymbolAddress((void**)&wkh, g_wk_hi);
  cudaGetSymbolAddress((void**)&wkl, g_wk_lo);
  cudaGetSymbolAddress((void**)&wvh, g_wv_hi);
  cudaGetSymbolAddress((void**)&wvl, g_wv_lo);
  cudaGetSymbolAddress((void**)&woh, g_wo_hi);
  cudaGetSymbolAddress((void**)&wol, g_wo_lo);

  static bool attr_done = false;
  if (!attr_done) {
    cudaFuncSetAttribute(gemm_mma_kernel<false>,
                         cudaFuncAttributeMaxDynamicSharedMemorySize, GEMM_SMEM);
    cudaFuncSetAttribute(gemm_mma_kernel<true>,
                         cudaFuncAttributeMaxDynamicSharedMemorySize, GEMM_SMEM);
    cudaFuncSetAttribute(fa_mma_kernel,
                         cudaFuncAttributeMaxDynamicSharedMemorySize, FA_SMEM);
    attr_done = true;
  }

  // split inputs / transpose+split weights
  {
    int nx = MTOK * DMODEL;
    split_kernel<<<(nx + 255) / 256, 256>>>(x, xh, xl, nx);
    dim3 blk(32, 8);
    transpose_split_kernel<<<dim3(DMODEL / 32, DMODEL / 32), blk>>>(wq, wqh, wql, DMODEL, DMODEL);
    transpose_split_kernel<<<dim3(KVDIM / 32, DMODEL / 32), blk>>>(wk, wkh, wkl, DMODEL, KVDIM);
    transpose_split_kernel<<<dim3(KVDIM / 32, DMODEL / 32), blk>>>(wv, wvh, wvl, DMODEL, KVDIM);
    transpose_split_kernel<<<dim3(DMODEL / 32, DMODEL / 32), blk>>>(wo, woh, wol, DMODEL, DMODEL);
  }

  // projections on tensor cores
  gemm_mma_kernel<false><<<dim3(DMODEL / 128, MTOK / 128), 256, GEMM_SMEM>>>(
      xh, xl, wqh, wql, q, nullptr, nullptr, MTOK, DMODEL, DMODEL);
  gemm_mma_kernel<false><<<dim3(KVDIM / 128, MTOK / 128), 256, GEMM_SMEM>>>(
      xh, xl, wkh, wkl, k, nullptr, nullptr, MTOK, KVDIM, DMODEL);
  gemm_mma_kernel<true><<<dim3(KVDIM / 128, MTOK / 128), 256, GEMM_SMEM>>>(
      xh, xl, wvh, wvl, nullptr, vh, vl, MTOK, KVDIM, DMODEL);

  // RoPE + scale + split
  {
    const float scale = 0.08838834764831845f;  // 1/sqrt(128)
    int tq = BATCH * SEQ * NH * (HD / 2);
    rope_split_kernel<<<(tq + 255) / 256, 256>>>(q, fcos, fsin, qh, ql, NH, scale);
    int tk = BATCH * SEQ * NKV * (HD / 2);
    rope_split_kernel<<<(tk + 255) / 256, 256>>>(k, fcos, fsin, kh, kl, NKV, 1.0f);
  }

  // Tensor-core flash attention on split operands
  fa_mma_kernel<<<dim3(SEQ / 64, NH, BATCH), 128, FA_SMEM>>>(
      qh, ql, kh, kl, vh, vl, aoh, aol);

  // Output projection on tensor cores
  gemm_mma_kernel<false><<<dim3(DMODEL / 128, MTOK / 128), 256, GEMM_SMEM>>>(
      aoh, aol, woh, wol, out, nullptr, nullptr, MTOK, DMODEL, DMODEL);
}

// round 9
// speedup vs baseline: 4.4790x; 1.3096x over previous
#include <cuda_runtime.h>
#include <cuda_fp16.h>
#include <cstdint>
#include <math.h>

// Problem dims (fixed by reference)
#define BATCH 2
#define SEQ 2048
#define DMODEL 2048
#define NH 16
#define NKV 4
#define HD 128
#define MTOK (BATCH * SEQ)          // 4096 tokens
#define KVDIM (NKV * HD)            // 512

// ---------------------------------------------------------------------------
// Scratch (device globals; runtime allocation is forbidden)
// ---------------------------------------------------------------------------
__device__ float g_q[MTOK * NH * HD];
__device__ float g_k[MTOK * KVDIM];

__device__ __half g_xh[MTOK * DMODEL];       // activations, single-rounded
__device__ __half g_aoh[MTOK * DMODEL];      // attention output, single-rounded
__device__ __half g_qh[MTOK * NH * HD];      // Q (pre-scaled), single
__device__ __half g_kh[MTOK * KVDIM];        // K hi
__device__ __half g_kl[MTOK * KVDIM];        // K residual * 2^10
__device__ __half g_vh[MTOK * KVDIM];        // V hi
__device__ __half g_vl[MTOK * KVDIM];        // V residual * 2^10
// weights transposed to [N, K]; lo = residual * 2^10
__device__ __half g_wq_h[DMODEL * DMODEL];
__device__ __half g_wq_l[DMODEL * DMODEL];
__device__ __half g_wk_h[KVDIM * DMODEL];
__device__ __half g_wk_l[KVDIM * DMODEL];
__device__ __half g_wv_h[KVDIM * DMODEL];
__device__ __half g_wv_l[KVDIM * DMODEL];
__device__ __half g_wo_h[DMODEL * DMODEL];
__device__ __half g_wo_l[DMODEL * DMODEL];

#define LO_SCALE 1024.0f
#define INV_LO_SCALE 0.0009765625f           // 2^-10
#define HSC2 0x14001400u                     // fp16x2 constant 2^-10

// ---------------------------------------------------------------------------
// helpers
// ---------------------------------------------------------------------------
__device__ __forceinline__ uint32_t smem_u32(const void* p) {
  uint32_t a;
  asm("{ .reg .u64 t; cvta.to.shared.u64 t, %1; cvt.u32.u64 %0, t; }"
      : "=r"(a) : "l"(p));
  return a;
}
__device__ __forceinline__ void cpa16(uint32_t s, const void* g) {
  asm volatile("cp.async.cg.shared.global [%0], [%1], 16;"
               :: "r"(s), "l"(g) : "memory");
}
__device__ __forceinline__ void cpa_commit() {
  asm volatile("cp.async.commit_group;" ::: "memory");
}
__device__ __forceinline__ void cpa_wait0() {
  asm volatile("cp.async.wait_group 0;" ::: "memory");
}
__device__ __forceinline__ void ldsm_x4(uint32_t addr, uint32_t* r) {
  asm volatile("ldmatrix.sync.aligned.m8n8.x4.shared.b16 {%0,%1,%2,%3}, [%4];"
               : "=r"(r[0]), "=r"(r[1]), "=r"(r[2]), "=r"(r[3]) : "r"(addr));
}
__device__ __forceinline__ void ldsm_x4_t(uint32_t addr, uint32_t* r) {
  asm volatile("ldmatrix.sync.aligned.m8n8.x4.trans.shared.b16 {%0,%1,%2,%3}, [%4];"
               : "=r"(r[0]), "=r"(r[1]), "=r"(r[2]), "=r"(r[3]) : "r"(addr));
}
__device__ __forceinline__ void mma_f16(float* d, const uint32_t* a,
                                        const uint32_t* b) {
  asm volatile(
      "mma.sync.aligned.m16n8k16.row.col.f32.f16.f16.f32 "
      "{%0,%1,%2,%3}, {%4,%5,%6,%7}, {%8,%9}, {%0,%1,%2,%3};"
      : "+f"(d[0]), "+f"(d[1]), "+f"(d[2]), "+f"(d[3])
      : "r"(a[0]), "r"(a[1]), "r"(a[2]), "r"(a[3]), "r"(b[0]), "r"(b[1]));
}
// pack: lo 16 bits = fp16(a), hi = fp16(b)
__device__ __forceinline__ uint32_t pack_f16(float a, float b) {
  uint32_t r;
  asm("cvt.rn.f16x2.f32 %0, %1, %2;" : "=r"(r) : "f"(b), "f"(a));
  return r;
}
__device__ __forceinline__ float f16_round(float f) {
  return __half2float(__float2half(f));
}
// multiply packed f16x2 by 2^-10 (exact power-of-2 scaling)
__device__ __forceinline__ uint32_t hscale(uint32_t x) {
  uint32_t r;
  asm("mul.f16x2 %0, %1, %2;" : "=r"(r) : "r"(x), "r"(HSC2));
  return r;
}

// ---------------------------------------------------------------------------
// Conversion kernels
// ---------------------------------------------------------------------------
__global__ void round_kernel(const float* __restrict__ src,
                             __half* __restrict__ dst, int n) {
  int i = blockIdx.x * blockDim.x + threadIdx.x;
  if (i >= n) return;
  dst[i] = __float2half(src[i]);
}

// w[K,N] fp32 -> th (fp16) / tl (residual*2^10 fp16), layout [N,K]
__global__ void transpose_split_kernel(const float* __restrict__ w,
                                       __half* __restrict__ th,
                                       __half* __restrict__ tl,
                                       int K, int N) {
  __shared__ float tile[32][33];
  int nx = blockIdx.x * 32 + threadIdx.x;
  int k0 = blockIdx.y * 32;
  for (int i = threadIdx.y; i < 32; i += 8)
    tile[i][threadIdx.x] = w[(size_t)(k0 + i) * N + nx];
  __syncthreads();
  for (int j = threadIdx.y; j < 32; j += 8) {
    int n = blockIdx.x * 32 + j;
    int kk = k0 + threadIdx.x;
    float f = tile[threadIdx.x][j];
    float h = f16_round(f);
    th[(size_t)n * K + kk] = __float2half(h);
    tl[(size_t)n * K + kk] = __float2half((f - h) * LO_SCALE);
  }
}

// RoPE + scale, single fp16 output (for Q)
__global__ void rope_single_kernel(const float* __restrict__ t,
                                   const float* __restrict__ fcos,
                                   const float* __restrict__ fsin,
                                   __half* __restrict__ th, int nheads,
                                   float scale) {
  int idx = blockIdx.x * blockDim.x + threadIdx.x;
  int total = BATCH * SEQ * nheads * (HD / 2);
  if (idx >= total) return;
  int p = idx & 63;
  int rest = idx >> 6;
  int h = rest % nheads;
  rest /= nheads;
  int s = rest & (SEQ - 1);
  int b = rest >> 11;
  float c = fcos[s * 64 + p];
  float sn = fsin[s * 64 + p];
  size_t off = ((size_t)(b * SEQ + s) * nheads + h) * HD + p * 2;
  const float* base = t + off;
  float x0 = base[0], x1 = base[1];
  float o0 = (x0 * c - x1 * sn) * scale;
  float o1 = (x0 * sn + x1 * c) * scale;
  *(uint32_t*)(th + off) = pack_f16(o0, o1);
}

// RoPE + split (hi, residual*2^10) fp16 outputs (for K)
__global__ void rope_split_kernel(const float* __restrict__ t,
                                  const float* __restrict__ fcos,
                                  const float* __restrict__ fsin,
                                  __half* __restrict__ th,
                                  __half* __restrict__ tl, int nheads) {
  int idx = blockIdx.x * blockDim.x + threadIdx.x;
  int total = BATCH * SEQ * nheads * (HD / 2);
  if (idx >= total) return;
  int p = idx & 63;
  int rest = idx >> 6;
  int h = rest % nheads;
  rest /= nheads;
  int s = rest & (SEQ - 1);
  int b = rest >> 11;
  float c = fcos[s * 64 + p];
  float sn = fsin[s * 64 + p];
  size_t off = ((size_t)(b * SEQ + s) * nheads + h) * HD + p * 2;
  const float* base = t + off;
  float x0 = base[0], x1 = base[1];
  float o0 = x0 * c - x1 * sn;
  float o1 = x0 * sn + x1 * c;
  *(uint32_t*)(th + off) = pack_f16(o0, o1);
  *(uint32_t*)(tl + off) = pack_f16((o0 - f16_round(o0)) * LO_SCALE,
                                    (o1 - f16_round(o1)) * LO_SCALE);
}

// ---------------------------------------------------------------------------
// mma.sync fp16 2-product GEMM with 2-stage cp.async pipeline.
// C[M,N] = A[M,K] @ Bt[N,K]^T, Bt = Bh + Bl*2^-10.
// 128x128 CTA tile, BK=32, 256 thr, 8 warps (warp tile 32x64).
// SPLIT_OUT: write fp16 hi + residual*2^10 instead of fp32.
// ---------------------------------------------------------------------------
#define SB 40
#define T2E (128 * SB)
#define STG_E (3 * T2E)
#define GEMM_SMEM (2 * STG_E * 2)      // 61440 B

template <bool SPLIT_OUT>
__global__ __launch_bounds__(256, 2) void gemm_mma_kernel(
    const __half* __restrict__ A, const __half* __restrict__ Bh,
    const __half* __restrict__ Bl, float* __restrict__ C,
    __half* __restrict__ Chi, __half* __restrict__ Clo, int M, int N, int K) {
  extern __shared__ __half smb[];
  const int tid = threadIdx.x;
  const int lane = tid & 31;
  const int wid = tid >> 5;
  const int wm = wid & 3;
  const int wn = wid >> 2;
  const int m0 = blockIdx.y * 128;
  const int n0 = blockIdx.x * 128;
  const uint32_t sbase = smem_u32(smb);

  const uint32_t OA = 0, OBH = T2E, OBL = 2 * T2E;

  float acc[2][8][4];
#pragma unroll
  for (int i = 0; i < 2; ++i)
#pragma unroll
    for (int j = 0; j < 8; ++j)
#pragma unroll
      for (int q = 0; q < 4; ++q) acc[i][j][q] = 0.f;

  const int a_row = lane & 15;
  const int a_col = (lane >> 4) * 8;
  const int b_row = (lane & 7) + ((lane & 16) >> 1);
  const int b_col = lane & 8;

  const int l_r = tid >> 2;
  const int l_c = (tid & 3) * 8;

  const int nchunks = K >> 5;

  {
#pragma unroll
    for (int it = 0; it < 2; ++it) {
      int r = l_r + it * 64;
      const size_t ga = (size_t)(m0 + r) * K + l_c;
      const size_t gb = (size_t)(n0 + r) * K + l_c;
      uint32_t so = (uint32_t)(r * SB + l_c) * 2;
      cpa16(sbase + OA * 2 + so, A + ga);
      cpa16(sbase + OBH * 2 + so, Bh + gb);
      cpa16(sbase + OBL * 2 + so, Bl + gb);
    }
    cpa_commit();
  }

  for (int c = 0; c < nchunks; ++c) {
    cpa_wait0();
    __syncthreads();
    if (c + 1 < nchunks) {
      const int k0g = (c + 1) << 5;
      const uint32_t stb = sbase + ((c + 1) & 1) * (STG_E * 2);
#pragma unroll
      for (int it = 0; it < 2; ++it) {
        int r = l_r + it * 64;
        const size_t ga = (size_t)(m0 + r) * K + k0g + l_c;
        const size_t gb = (size_t)(n0 + r) * K + k0g + l_c;
        uint32_t so = (uint32_t)(r * SB + l_c) * 2;
        cpa16(stb + OA * 2 + so, A + ga);
        cpa16(stb + OBH * 2 + so, Bh + gb);
        cpa16(stb + OBL * 2 + so, Bl + gb);
      }
      cpa_commit();
    }

    const uint32_t stg = sbase + (c & 1) * (STG_E * 2);
#pragma unroll
    for (int s = 0; s < 2; ++s) {
      const int k0 = s * 16;
      uint32_t af[2][4], afs[2][4];
#pragma unroll
      for (int mt = 0; mt < 2; ++mt) {
        uint32_t off = (uint32_t)((wm * 32 + mt * 16 + a_row) * SB + k0 + a_col) * 2;
        ldsm_x4(stg + OA * 2 + off, af[mt]);
#pragma unroll
        for (int qq = 0; qq < 4; ++qq) afs[mt][qq] = hscale(af[mt][qq]);
      }
#pragma unroll
      for (int nt2 = 0; nt2 < 4; ++nt2) {
        uint32_t bh[4], bl[4];
        uint32_t off = (uint32_t)((wn * 64 + nt2 * 16 + b_row) * SB + k0 + b_col) * 2;
        ldsm_x4(stg + OBH * 2 + off, bh);
        ldsm_x4(stg + OBL * 2 + off, bl);
#pragma unroll
        for (int mt = 0; mt < 2; ++mt) {
          mma_f16(acc[mt][nt2 * 2], af[mt], bh);
          mma_f16(acc[mt][nt2 * 2], afs[mt], bl);
          mma_f16(acc[mt][nt2 * 2 + 1], af[mt], bh + 2);
          mma_f16(acc[mt][nt2 * 2 + 1], afs[mt], bl + 2);
        }
      }
    }
  }

#pragma unroll
  for (int mt = 0; mt < 2; ++mt) {
    int r0 = m0 + wm * 32 + mt * 16 + (lane >> 2);
#pragma unroll
    for (int nt = 0; nt < 8; ++nt) {
      int col = n0 + wn * 64 + nt * 8 + (lane & 3) * 2;
      if (SPLIT_OUT) {
        float a0 = acc[mt][nt][0], a1 = acc[mt][nt][1];
        float b0 = acc[mt][nt][2], b1 = acc[mt][nt][3];
        *(uint32_t*)(Chi + (size_t)r0 * N + col) = pack_f16(a0, a1);
        *(uint32_t*)(Clo + (size_t)r0 * N + col) =
            pack_f16((a0 - f16_round(a0)) * LO_SCALE,
                     (a1 - f16_round(a1)) * LO_SCALE);
        *(uint32_t*)(Chi + (size_t)(r0 + 8) * N + col) = pack_f16(b0, b1);
        *(uint32_t*)(Clo + (size_t)(r0 + 8) * N + col) =
            pack_f16((b0 - f16_round(b0)) * LO_SCALE,
                     (b1 - f16_round(b1)) * LO_SCALE);
      } else {
        float2 v0 = {acc[mt][nt][0], acc[mt][nt][1]};
        float2 v1 = {acc[mt][nt][2], acc[mt][nt][3]};
        *(float2*)(C + (size_t)r0 * N + col) = v0;
        *(float2*)(C + (size_t)(r0 + 8) * N + col) = v1;
      }
    }
  }
}

// ---------------------------------------------------------------------------
// Tensor-core flash attention, fp16 2-product, causal.
// BLOCK_M=64 (4 warps x m16), BLOCK_N=64, D=128. 87 KB smem -> 2 CTAs/SM.
// ---------------------------------------------------------------------------
#define FSD 136                       // smem stride (elements)
#define FTE (64 * FSD)                // elements per tile
#define FA_SMEM (5 * FTE * 2)         // Q,Kh,Kl,Vh,Vl = 87040 B

__global__ __launch_bounds__(128) void fa_mma_kernel(
    const __half* __restrict__ qh, const __half* __restrict__ kh,
    const __half* __restrict__ kl, const __half* __restrict__ vh,
    const __half* __restrict__ vl, __half* __restrict__ ao) {
  extern __shared__ __half fsm[];
  const uint32_t sbase = smem_u32(fsm);
  const int tid = threadIdx.x;
  const int lane = tid & 31;
  const int w = tid >> 5;

  const int mt = gridDim.x - 1 - blockIdx.x;   // heavy tiles first
  const int m0 = mt * 64;
  const int h = blockIdx.y;
  const int b = blockIdx.z;
  const int g = h >> 2;

  const uint32_t QO = 0, KHO = FTE, KLO = 2 * FTE, VHO = 3 * FTE,
                 VLO = 4 * FTE;

  // --- async-load Q tile (pre-scaled fp16) ---
  {
    const int r = tid >> 4;
    const int cvec = (tid & 15) * 8;
#pragma unroll
    for (int it = 0; it < 8; ++it) {
      int row = r + it * 8;
      size_t gi = ((size_t)(b * SEQ + m0 + row) * NH + h) * HD + cvec;
      cpa16(sbase + (QO + (uint32_t)(row * FSD + cvec)) * 2, qh + gi);
    }
    cpa_commit();
  }

  float m_lo = -1e30f, m_hi = -1e30f, l_lo = 0.f, l_hi = 0.f;
  float oacc[16][4];
#pragma unroll
  for (int i = 0; i < 16; ++i)
#pragma unroll
    for (int j = 0; j < 4; ++j) oacc[i][j] = 0.f;

  const int a_row = lane & 15;
  const int a_col = (lane >> 4) * 8;
  const int b_row = (lane & 7) + ((lane & 16) >> 1);
  const int b_col = lane & 8;

  for (int t = 0; t <= mt; ++t) {
    const int n0 = t * 64;
    __syncthreads();                   // previous compute done
    {
      const int r = tid >> 4;
      const int cvec = (tid & 15) * 8;
#pragma unroll
      for (int it = 0; it < 8; ++it) {
        int row = r + it * 8;
        size_t gi = ((size_t)(b * SEQ + n0 + row) * NKV + g) * HD + cvec;
        uint32_t e = (uint32_t)(row * FSD + cvec) * 2;
        cpa16(sbase + KHO * 2 + e, kh + gi);
        cpa16(sbase + KLO * 2 + e, kl + gi);
        cpa16(sbase + VHO * 2 + e, vh + gi);
        cpa16(sbase + VLO * 2 + e, vl + gi);
      }
      cpa_commit();
    }
    cpa_wait0();
    __syncthreads();

    // --- S = Q @ (Kh + Kl*2^-10)^T ---
    float sacc[8][4];
#pragma unroll
    for (int i = 0; i < 8; ++i)
#pragma unroll
      for (int j = 0; j < 4; ++j) sacc[i][j] = 0.f;

#pragma unroll
    for (int kc = 0; kc < 8; ++kc) {
      uint32_t aq_off = (uint32_t)((w * 16 + a_row) * FSD + kc * 16 + a_col) * 2;
      uint32_t aq[4], aqs[4];
      ldsm_x4(sbase + QO * 2 + aq_off, aq);
#pragma unroll
      for (int qq = 0; qq < 4; ++qq) aqs[qq] = hscale(aq[qq]);
#pragma unroll
      for (int np = 0; np < 4; ++np) {
        uint32_t bo = (uint32_t)((np * 16 + b_row) * FSD + kc * 16 + b_col) * 2;
        uint32_t bh[4], bl[4];
        ldsm_x4(sbase + KHO * 2 + bo, bh);
        ldsm_x4(sbase + KLO * 2 + bo, bl);
        mma_f16(sacc[np * 2], aq, bh);
        mma_f16(sacc[np * 2], aqs, bl);
        mma_f16(sacc[np * 2 + 1], aq, bh + 2);
        mma_f16(sacc[np * 2 + 1], aqs, bl + 2);
      }
    }

    if (t == mt) {
      int row_lo = w * 16 + (lane >> 2);
      int row_hi = row_lo + 8;
#pragma unroll
      for (int nt = 0; nt < 8; ++nt) {
        int c0 = nt * 8 + (lane & 3) * 2;
        if (c0 > row_lo) sacc[nt][0] = -1e30f;
        if (c0 + 1 > row_lo) sacc[nt][1] = -1e30f;
        if (c0 > row_hi) sacc[nt][2] = -1e30f;
        if (c0 + 1 > row_hi) sacc[nt][3] = -1e30f;
      }
    }

    // --- online softmax ---
    float rmax_lo = -1e30f, rmax_hi = -1e30f;
#pragma unroll
    for (int nt = 0; nt < 8; ++nt) {
      rmax_lo = fmaxf(rmax_lo, fmaxf(sacc[nt][0], sacc[nt][1]));
      rmax_hi = fmaxf(rmax_hi, fmaxf(sacc[nt][2], sacc[nt][3]));
    }
#pragma unroll
    for (int d = 1; d < 4; d <<= 1) {
      rmax_lo = fmaxf(rmax_lo, __shfl_xor_sync(0xffffffffu, rmax_lo, d));
      rmax_hi = fmaxf(rmax_hi, __shfl_xor_sync(0xffffffffu, rmax_hi, d));
    }
    float mn_lo = fmaxf(m_lo, rmax_lo);
    float mn_hi = fmaxf(m_hi, rmax_hi);
    float f_lo = __expf(m_lo - mn_lo);
    float f_hi = __expf(m_hi - mn_hi);
    m_lo = mn_lo; m_hi = mn_hi;

    float rsum_lo = 0.f, rsum_hi = 0.f;
#pragma unroll
    for (int nt = 0; nt < 8; ++nt) {
      sacc[nt][0] = __expf(sacc[nt][0] - mn_lo);
      sacc[nt][1] = __expf(sacc[nt][1] - mn_lo);
      sacc[nt][2] = __expf(sacc[nt][2] - mn_hi);
      sacc[nt][3] = __expf(sacc[nt][3] - mn_hi);
      rsum_lo += sacc[nt][0] + sacc[nt][1];
      rsum_hi += sacc[nt][2] + sacc[nt][3];
    }
#pragma unroll
    for (int d = 1; d < 4; d <<= 1) {
      rsum_lo += __shfl_xor_sync(0xffffffffu, rsum_lo, d);
      rsum_hi += __shfl_xor_sync(0xffffffffu, rsum_hi, d);
    }
    l_lo = l_lo * f_lo + rsum_lo;
    l_hi = l_hi * f_hi + rsum_hi;
#pragma unroll
    for (int i = 0; i < 16; ++i) {
      oacc[i][0] *= f_lo; oacc[i][1] *= f_lo;
      oacc[i][2] *= f_hi; oacc[i][3] *= f_hi;
    }

    // --- O += P @ (Vh + Vl*2^-10) ---
#pragma unroll
    for (int kt = 0; kt < 4; ++kt) {
      const float* s0 = sacc[2 * kt];
      const float* s1 = sacc[2 * kt + 1];
      uint32_t ph[4], ps[4];
      ph[0] = pack_f16(s0[0], s0[1]);
      ph[1] = pack_f16(s0[2], s0[3]);
      ph[2] = pack_f16(s1[0], s1[1]);
      ph[3] = pack_f16(s1[2], s1[3]);
      ps[0] = pack_f16(s0[0] * INV_LO_SCALE, s0[1] * INV_LO_SCALE);
      ps[1] = pack_f16(s0[2] * INV_LO_SCALE, s0[3] * INV_LO_SCALE);
      ps[2] = pack_f16(s1[0] * INV_LO_SCALE, s1[1] * INV_LO_SCALE);
      ps[3] = pack_f16(s1[2] * INV_LO_SCALE, s1[3] * INV_LO_SCALE);
#pragma unroll
      for (int dp = 0; dp < 8; ++dp) {
        uint32_t vo = (uint32_t)((kt * 16 + (lane & 15)) * FSD + dp * 16 +
                                 ((lane >> 4) << 3)) * 2;
        uint32_t vhf[4], vlf[4];
        ldsm_x4_t(sbase + VHO * 2 + vo, vhf);
        ldsm_x4_t(sbase + VLO * 2 + vo, vlf);
        mma_f16(oacc[dp * 2], ph, vhf);
        mma_f16(oacc[dp * 2], ps, vlf);
        mma_f16(oacc[dp * 2 + 1], ph, vhf + 2);
        mma_f16(oacc[dp * 2 + 1], ps, vlf + 2);
      }
    }
  }

  // --- epilogue: normalize, round to fp16, write [b,s,h,d] ---
  float inv_lo = 1.f / l_lo;
  float inv_hi = 1.f / l_hi;
  int r_lo = m0 + w * 16 + (lane >> 2);
  int r_hi = r_lo + 8;
#pragma unroll
  for (int dt = 0; dt < 16; ++dt) {
    int col = dt * 8 + (lane & 3) * 2;
    size_t i0 = ((size_t)(b * SEQ + r_lo) * NH + h) * HD + col;
    size_t i1 = ((size_t)(b * SEQ + r_hi) * NH + h) * HD + col;
    *(uint32_t*)(ao + i0) = pack_f16(oacc[dt][0] * inv_lo, oacc[dt][1] * inv_lo);
    *(uint32_t*)(ao + i1) = pack_f16(oacc[dt][2] * inv_hi, oacc[dt][3] * inv_hi);
  }
}

// ---------------------------------------------------------------------------
// Launch
// ---------------------------------------------------------------------------
extern "C" void kernel_launch(void* const* d_in, const int* in_sizes, int n_in,
                              void* d_out, int out_size) {
  const float* x    = (const float*)d_in[0];
  const float* fcos = (const float*)d_in[1];
  const float* fsin = (const float*)d_in[2];
  // d_in[3] = mask (causal mask applied analytically)
  const float* wq = (const float*)d_in[4];
  const float* wk = (const float*)d_in[5];
  const float* wv = (const float*)d_in[6];
  const float* wo = (const float*)d_in[7];
  float* out = (float*)d_out;

  float *q, *k;
  cudaGetSymbolAddress((void**)&q, g_q);
  cudaGetSymbolAddress((void**)&k, g_k);
  __half *xh, *aoh, *qh, *kh, *kl, *vh, *vl;
  __half *wqh, *wql, *wkh, *wkl, *wvh, *wvl, *woh, *wol;
  cudaGetSymbolAddress((void**)&xh, g_xh);
  cudaGetSymbolAddress((void**)&aoh, g_aoh);
  cudaGetSymbolAddress((void**)&qh, g_qh);
  cudaGetSymbolAddress((void**)&kh, g_kh);
  cudaGetSymbolAddress((void**)&kl, g_kl);
  cudaGetSymbolAddress((void**)&vh, g_vh);
  cudaGetSymbolAddress((void**)&vl, g_vl);
  cudaGetSymbolAddress((void**)&wqh, g_wq_h);
  cudaGetSymbolAddress((void**)&wql, g_wq_l);
  cudaGetSymbolAddress((void**)&wkh, g_wk_h);
  cudaGetSymbolAddress((void**)&wkl, g_wk_l);
  cudaGetSymbolAddress((void**)&wvh, g_wv_h);
  cudaGetSymbolAddress((void**)&wvl, g_wv_l);
  cudaGetSymbolAddress((void**)&woh, g_wo_h);
  cudaGetSymbolAddress((void**)&wol, g_wo_l);

  static bool attr_done = false;
  if (!attr_done) {
    cudaFuncSetAttribute(gemm_mma_kernel<false>,
                         cudaFuncAttributeMaxDynamicSharedMemorySize, GEMM_SMEM);
    cudaFuncSetAttribute(gemm_mma_kernel<true>,
                         cudaFuncAttributeMaxDynamicSharedMemorySize, GEMM_SMEM);
    cudaFuncSetAttribute(fa_mma_kernel,
                         cudaFuncAttributeMaxDynamicSharedMemorySize, FA_SMEM);
    attr_done = true;
  }

  // round x / transpose+split weights (lo scaled by 2^10)
  {
    int nx = MTOK * DMODEL;
    round_kernel<<<(nx + 255) / 256, 256>>>(x, xh, nx);
    dim3 blk(32, 8);
    transpose_split_kernel<<<dim3(DMODEL / 32, DMODEL / 32), blk>>>(wq, wqh, wql, DMODEL, DMODEL);
    transpose_split_kernel<<<dim3(KVDIM / 32, DMODEL / 32), blk>>>(wk, wkh, wkl, DMODEL, KVDIM);
    transpose_split_kernel<<<dim3(KVDIM / 32, DMODEL / 32), blk>>>(wv, wvh, wvl, DMODEL, KVDIM);
    transpose_split_kernel<<<dim3(DMODEL / 32, DMODEL / 32), blk>>>(wo, woh, wol, DMODEL, DMODEL);
  }

  // projections on tensor cores (fp16 2-product)
  gemm_mma_kernel<false><<<dim3(DMODEL / 128, MTOK / 128), 256, GEMM_SMEM>>>(
      xh, wqh, wql, q, nullptr, nullptr, MTOK, DMODEL, DMODEL);
  gemm_mma_kernel<false><<<dim3(KVDIM / 128, MTOK / 128), 256, GEMM_SMEM>>>(
      xh, wkh, wkl, k, nullptr, nullptr, MTOK, KVDIM, DMODEL);
  gemm_mma_kernel<true><<<dim3(KVDIM / 128, MTOK / 128), 256, GEMM_SMEM>>>(
      xh, wvh, wvl, nullptr, vh, vl, MTOK, KVDIM, DMODEL);

  // RoPE: Q single (pre-scaled), K split
  {
    const float scale = 0.08838834764831845f;  // 1/sqrt(128)
    int tq = BATCH * SEQ * NH * (HD / 2);
    rope_single_kernel<<<(tq + 255) / 256, 256>>>(q, fcos, fsin, qh, NH, scale);
    int tk = BATCH * SEQ * NKV * (HD / 2);
    rope_split_kernel<<<(tk + 255) / 256, 256>>>(k, fcos, fsin, kh, kl, NKV);
  }

  // Tensor-core flash attention -> fp16 attention output
  fa_mma_kernel<<<dim3(SEQ / 64, NH, BATCH), 128, FA_SMEM>>>(
      qh, kh, kl, vh, vl, aoh);

  // Output projection
  gemm_mma_kernel<false><<<dim3(DMODEL / 128, MTOK / 128), 256, GEMM_SMEM>>>(
      aoh, woh, wol, out, nullptr, nullptr, MTOK, DMODEL, DMODEL);
}